// round 13
// baseline (speedup 1.0000x reference)
#include <cuda_runtime.h>
#include <cuda_bf16.h>
#include <cuda_fp16.h>
#include <math.h>

#define N_ 100000
#define E_ 500000
#define D_ 128
#define T_ 3
#define R_ 4
#define H_ 8
#define ML_ 240
#define TD_ ((size_t)N_*(size_t)D_)
#define PAD_ 136
#define BDPAD_ 24
#define BDSZ_ (H_*16*BDPAD_)
#define GEMM_SMEM (4 * 128 * PAD_ * 2)
#define QKVR_SMEM ((4 * 128 * PAD_ + 2 * R_ * BDSZ_) * 2)
#define NMAT_ 9
#define NPB_ ((N_ + 127) / 128)
#define NB_  (R_ * NPB_)

__device__ float g_x[TD_];
__device__ __half g_Qh[TD_];
__device__ float g_aggr[2][TD_];          // per-layer unnormalized U
__device__ float g_den[2][N_*H_];
__device__ __half g_KVrh[(size_t)R_*N_*2*D_];   // K at +0, V at +128 (per node)
__device__ float g_rte_tab[ML_*2*D_];
__device__ float g_rte_proj[ML_*D_];
__device__ __half g_tabKVh[2][(size_t)R_*T_*ML_*2*D_];  // K at +0, V at +128
__device__ __nv_bfloat16 g_Wh[(size_t)NMAT_*T_*D_*D_];
__device__ __nv_bfloat16 g_Wl[(size_t)NMAT_*T_*D_*D_];
__device__ __nv_bfloat16 g_BDh[2*2*R_*BDSZ_];
__device__ __nv_bfloat16 g_BDl[2*2*R_*BDSZ_];
__device__ int   g_typeList[T_][N_];
__device__ int   g_typeCnt[T_];
__device__ int   g_bCnt[NB_];
__device__ int   g_bOff[NB_+1];
__device__ int   g_bFill[NB_];
__device__ int   g_eS[E_];
__device__ int   g_eT[E_];
__device__ int   g_eMeta[E_];   // st | tt<<2 | time<<4

__device__ __forceinline__ float gelu_f(float x) { return x * normcdff(x); }

__device__ __forceinline__ void red_add_v4(float* p, float a, float b, float c, float d) {
    asm volatile("red.global.add.v4.f32 [%0], {%1,%2,%3,%4};"
                 :: "l"(p), "f"(a), "f"(b), "f"(c), "f"(d) : "memory");
}

// ---------------- mma helpers ----------------
__device__ __forceinline__ void ldsm4(unsigned& r0, unsigned& r1, unsigned& r2, unsigned& r3,
                                      unsigned addr) {
    asm volatile("ldmatrix.sync.aligned.m8n8.x4.shared.b16 {%0,%1,%2,%3}, [%4];"
                 : "=r"(r0), "=r"(r1), "=r"(r2), "=r"(r3) : "r"(addr));
}
__device__ __forceinline__ void ldsm4t(unsigned& r0, unsigned& r1, unsigned& r2, unsigned& r3,
                                       unsigned addr) {
    asm volatile("ldmatrix.sync.aligned.m8n8.x4.trans.shared.b16 {%0,%1,%2,%3}, [%4];"
                 : "=r"(r0), "=r"(r1), "=r"(r2), "=r"(r3) : "r"(addr));
}
__device__ __forceinline__ void mma16816(float* d, const unsigned* a, const unsigned* b) {
    asm volatile("mma.sync.aligned.m16n8k16.row.col.f32.bf16.bf16.f32 "
                 "{%0,%1,%2,%3}, {%4,%5,%6,%7}, {%8,%9}, {%0,%1,%2,%3};"
                 : "+f"(d[0]), "+f"(d[1]), "+f"(d[2]), "+f"(d[3])
                 : "r"(a[0]), "r"(a[1]), "r"(a[2]), "r"(a[3]), "r"(b[0]), "r"(b[1]));
}
__device__ __forceinline__ unsigned pack_bf2(__nv_bfloat16 a, __nv_bfloat16 b) {
    __nv_bfloat162 p(a, b);
    return *reinterpret_cast<unsigned*>(&p);
}

// ---------------- precompute kernels ----------------
__global__ void k_rte_tab() {
    int pos = blockIdx.x;
    int i   = threadIdx.x;
    const float s = 0.08838834764831845f;
    float div;
    if (i >= 5) div = 0.f;   // fp32 10000^ar overflow -> inf -> 0
    else {
        float pf = (float)pow(10000.0, (double)(2 * i));
        div = 1.0f / ((pf / 128.0f) / 2.0f);
    }
    float ang = (float)pos * div;
    double a = (double)ang;
    g_rte_tab[pos * 256 + 2 * i]     = (float)sin(a) * s;
    g_rte_tab[pos * 256 + 2 * i + 1] = (float)cos(a) * s;
}

__global__ void k_rte_proj(const float* __restrict__ w, const float* __restrict__ b) {
    int time = blockIdx.x;
    int d    = threadIdx.x;
    float acc = b[d];
    const float* tr = g_rte_tab + time * 256;
    for (int c = 0; c < 256; c++) acc += tr[c] * w[c * 128 + d];
    g_rte_proj[time * 128 + d] = acc;
}

__global__ void k_tables(const float* __restrict__ Wk, const float* __restrict__ Wv,
                         const float* __restrict__ relAtt, const float* __restrict__ relMsg,
                         int l) {
    __shared__ float sK[128], sV[128];
    int id = blockIdx.x;
    int d  = threadIdx.x;
    int t = id / ML_, time = id % ML_;
    const float* pr = g_rte_proj + time * 128;
    const float* wk = Wk + (size_t)t * 128 * 128;
    const float* wv = Wv + (size_t)t * 128 * 128;
    float aK = 0.f, aV = 0.f;
    for (int k = 0; k < 128; k++) {
        float p = pr[k];
        aK += p * wk[k * 128 + d];
        aV += p * wv[k * 128 + d];
    }
    sK[d] = aK; sV[d] = aV;
    __syncthreads();
    int h = d >> 4, dk = d & 15;
    size_t rowoff = (size_t)(t * ML_ + time) * 256 + d;
    for (int r = 0; r < R_; r++) {
        const float* A = relAtt + ((size_t)r * H_ + h) * 256;
        const float* M = relMsg + ((size_t)r * H_ + h) * 256;
        float k2 = 0.f, v2 = 0.f;
        #pragma unroll
        for (int j = 0; j < 16; j++) {
            k2 += sK[h * 16 + j] * A[j * 16 + dk];
            v2 += sV[h * 16 + j] * M[j * 16 + dk];
        }
        g_tabKVh[l][(size_t)r * T_ * ML_ * 256 + rowoff]       = __float2half_rn(k2);
        g_tabKVh[l][(size_t)r * T_ * ML_ * 256 + rowoff + 128] = __float2half_rn(v2);
    }
}

__global__ void k_wsplit(const float* __restrict__ src, int midx) {
    int i = blockIdx.x * blockDim.x + threadIdx.x;
    int n = T_ * D_ * D_;
    if (i >= n) return;
    size_t off = (size_t)midx * n + i;
    float v = src[i];
    __nv_bfloat16 h = __float2bfloat16_rn(v);
    g_Wh[off] = h;
    g_Wl[off] = __float2bfloat16_rn(v - __bfloat162float(h));
}

__global__ void k_relsplit(const float* __restrict__ relAtt, const float* __restrict__ relMsg) {
    int idx = blockIdx.x * blockDim.x + threadIdx.x;
    if (idx >= 2 * 2 * R_ * H_ * 256) return;
    int c = idx & 15, k = (idx >> 4) & 15, h = (idx >> 8) & 7;
    int r = (idx >> 11) & 3, w = (idx >> 13) & 1, l = idx >> 14;
    const float* src = w ? relMsg : relAtt;
    float v = src[(((size_t)l * R_ + r) * H_ + h) * 256 + k * 16 + c];
    __nv_bfloat16 hi = __float2bfloat16_rn(v);
    size_t dst = (size_t)(((l * 2 + w) * R_ + r)) * BDSZ_ + (h * 16 + k) * BDPAD_ + c;
    g_BDh[dst] = hi;
    g_BDl[dst] = __float2bfloat16_rn(v - __bfloat162float(hi));
}

// ---------------- bucketing ----------------
__global__ void k_init_bkt() {
    int i = blockIdx.x * blockDim.x + threadIdx.x;
    if (i < NB_) { g_bCnt[i] = 0; g_bFill[i] = 0; }
}

__global__ void k_init_type() {
    if (threadIdx.x < T_) g_typeCnt[threadIdx.x] = 0;
}

__global__ void k_build_type(const int* __restrict__ nt) {
    __shared__ int c[T_];
    __shared__ int base[T_];
    int tid = threadIdx.x;
    if (tid < T_) c[tid] = 0;
    __syncthreads();
    int i = blockIdx.x * blockDim.x + tid;
    int t = -1, rank = 0;
    if (i < N_) { t = nt[i]; rank = atomicAdd(&c[t], 1); }
    __syncthreads();
    if (tid < T_) base[tid] = c[tid] ? atomicAdd(&g_typeCnt[tid], c[tid]) : 0;
    __syncthreads();
    if (i < N_) g_typeList[t][base[t] + rank] = i;
}

__global__ void k_count_b(const int* __restrict__ tgt, const int* __restrict__ et) {
    int i = blockIdx.x * blockDim.x + threadIdx.x;
    if (i < E_) atomicAdd(&g_bCnt[et[i] * NPB_ + (tgt[i] >> 7)], 1);
}

__global__ void __launch_bounds__(1024) k_scan_b() {
    __shared__ int wsum[32];
    int tid = threadIdx.x;
    int v[4], s = 0;
    #pragma unroll
    for (int i = 0; i < 4; i++) {
        int idx = tid * 4 + i;
        v[i] = (idx < NB_) ? g_bCnt[idx] : 0;
        s += v[i];
    }
    int lane = tid & 31, w = tid >> 5;
    int incl = s;
    #pragma unroll
    for (int d = 1; d < 32; d <<= 1) {
        int o = __shfl_up_sync(0xffffffffu, incl, d);
        if (lane >= d) incl += o;
    }
    if (lane == 31) wsum[w] = incl;
    __syncthreads();
    if (w == 0) {
        int x = (lane < 32) ? wsum[lane] : 0;
        int in2 = x;
        #pragma unroll
        for (int d = 1; d < 32; d <<= 1) {
            int o = __shfl_up_sync(0xffffffffu, in2, d);
            if (lane >= d) in2 += o;
        }
        wsum[lane] = in2 - x;
    }
    __syncthreads();
    int excl = wsum[w] + incl - s;
    #pragma unroll
    for (int i = 0; i < 4; i++) {
        int idx = tid * 4 + i;
        if (idx < NB_) g_bOff[idx] = excl;
        excl += v[i];
    }
    if (tid == 1023) g_bOff[NB_] = E_;
}

__global__ void k_scatter_b(const int* __restrict__ src, const int* __restrict__ tgt,
                            const int* __restrict__ et, const int* __restrict__ etm,
                            const int* __restrict__ nt) {
    int e = blockIdx.x * blockDim.x + threadIdx.x;
    if (e < E_) {
        int t = tgt[e];
        int key = et[e] * NPB_ + (t >> 7);
        int p = g_bOff[key] + atomicAdd(&g_bFill[key], 1);
        int s = src[e];
        g_eS[p] = s;
        g_eT[p] = t;
        g_eMeta[p] = nt[s] | (nt[t] << 2) | (etm[e] << 4);
    }
}

__global__ void k_init_layer() {
    size_t stride = (size_t)gridDim.x * blockDim.x;
    size_t i0 = (size_t)blockIdx.x * blockDim.x + threadIdx.x;
    for (size_t i = i0; i < 2 * (size_t)N_ * H_; i += stride) g_den[0][i] = 0.f;
    for (size_t i = i0; i < 2 * TD_; i += stride) g_aggr[0][i] = 0.f;
}

// ---------------- GEMM building blocks ----------------
__device__ __forceinline__ void load_w_smem(__nv_bfloat16* sWh, __nv_bfloat16* sWl,
                                            int midx, int t, int tid) {
    size_t base = ((size_t)midx * T_ + t) * D_ * D_;
    const uint4* wh4 = (const uint4*)(g_Wh + base);
    const uint4* wl4 = (const uint4*)(g_Wl + base);
    #pragma unroll
    for (int it = 0; it < 8; it++) {
        int idx = it * 256 + tid;
        int row = idx >> 4;
        int col = (idx & 15) * 8;
        *(uint4*)(sWh + row * PAD_ + col) = wh4[idx];
        *(uint4*)(sWl + row * PAD_ + col) = wl4[idx];
    }
}

__device__ __forceinline__ void cvt_store(__nv_bfloat16* sAh, __nv_bfloat16* sAl,
                                          int row, int col, float4 v) {
    __nv_bfloat16 h0 = __float2bfloat16_rn(v.x), h1 = __float2bfloat16_rn(v.y);
    __nv_bfloat16 h2 = __float2bfloat16_rn(v.z), h3 = __float2bfloat16_rn(v.w);
    __nv_bfloat16 l0 = __float2bfloat16_rn(v.x - __bfloat162float(h0));
    __nv_bfloat16 l1 = __float2bfloat16_rn(v.y - __bfloat162float(h1));
    __nv_bfloat16 l2 = __float2bfloat16_rn(v.z - __bfloat162float(h2));
    __nv_bfloat16 l3 = __float2bfloat16_rn(v.w - __bfloat162float(h3));
    *(uint2*)(sAh + row * PAD_ + col) = make_uint2(pack_bf2(h0, h1), pack_bf2(h2, h3));
    *(uint2*)(sAl + row * PAD_ + col) = make_uint2(pack_bf2(l0, l1), pack_bf2(l2, l3));
}

// inop: 0=none, 1=gelu(v), 2=gelu(v/den)
__device__ __forceinline__ void load_a_smem(__nv_bfloat16* sAh, __nv_bfloat16* sAl,
                                            const float* __restrict__ in,
                                            const int* sList, int inop, int tid,
                                            const float* __restrict__ den) {
    #pragma unroll
    for (int it = 0; it < 16; it++) {
        int idx = it * 256 + tid;
        int row = idx >> 5;
        int col = (idx & 31) << 2;
        int grow = sList[row];
        float4 v = *(const float4*)(in + (size_t)grow * D_ + col);
        if (inop == 1) {
            v.x = gelu_f(v.x); v.y = gelu_f(v.y); v.z = gelu_f(v.z); v.w = gelu_f(v.w);
        } else if (inop == 2) {
            float dv = den[grow * H_ + (col >> 4)];
            float inv = dv > 0.f ? 1.f / dv : 0.f;
            v.x = gelu_f(v.x * inv); v.y = gelu_f(v.y * inv);
            v.z = gelu_f(v.z * inv); v.w = gelu_f(v.w * inv);
        }
        cvt_store(sAh, sAl, row, col, v);
    }
}

__device__ __forceinline__ void mma_tile(float (&acc)[2][8][4],
                                         const __nv_bfloat16* sAh, const __nv_bfloat16* sAl,
                                         const __nv_bfloat16* sWh, const __nv_bfloat16* sWl,
                                         int mbase, int nbase, int lane) {
    int aRow = mbase + (lane & 15);
    int aColAdd = (lane >> 4) << 3;
    int bg = lane >> 3;
    int bRowAdd = ((bg & 1) << 3) + (lane & 7);
    int bColAdd = (bg >> 1) << 3;

    unsigned aHbase = (unsigned)__cvta_generic_to_shared(sAh + aRow * PAD_);
    unsigned aLbase = (unsigned)__cvta_generic_to_shared(sAl + aRow * PAD_);
    unsigned wHbase = (unsigned)__cvta_generic_to_shared(sWh);
    unsigned wLbase = (unsigned)__cvta_generic_to_shared(sWl);

    #pragma unroll
    for (int kc = 0; kc < 8; kc++) {
        int k0 = kc * 16;
        unsigned ah[2][4], al[2][4];
        #pragma unroll
        for (int mt = 0; mt < 2; mt++) {
            unsigned off = (mt * 16 * PAD_ + k0 + aColAdd) * 2;
            ldsm4(ah[mt][0], ah[mt][1], ah[mt][2], ah[mt][3], aHbase + off);
            ldsm4(al[mt][0], al[mt][1], al[mt][2], al[mt][3], aLbase + off);
        }
        #pragma unroll
        for (int nt2 = 0; nt2 < 4; nt2++) {
            int nb = nbase + nt2 * 16;
            unsigned off = ((k0 + bRowAdd) * PAD_ + nb + bColAdd) * 2;
            unsigned bh[4], bl[4];
            ldsm4t(bh[0], bh[1], bh[2], bh[3], wHbase + off);
            ldsm4t(bl[0], bl[1], bl[2], bl[3], wLbase + off);
            #pragma unroll
            for (int mt = 0; mt < 2; mt++) {
                mma16816(acc[mt][nt2 * 2],     ah[mt], bh);
                mma16816(acc[mt][nt2 * 2],     al[mt], bh);
                mma16816(acc[mt][nt2 * 2],     ah[mt], bl);
                mma16816(acc[mt][nt2 * 2 + 1], ah[mt], bh + 2);
                mma16816(acc[mt][nt2 * 2 + 1], al[mt], bh + 2);
                mma16816(acc[mt][nt2 * 2 + 1], ah[mt], bl + 2);
            }
        }
    }
}

// block-diag relation transform of tile in sTh/sTl; scatter fp16 to
// KVout[r][node][koff + 0..127] (interleaved K/V layout, node stride 256).
__device__ __forceinline__ void bd_transform_store(
    const __nv_bfloat16* sTh, const __nv_bfloat16* sTl,
    const __nv_bfloat16* sBDh, const __nv_bfloat16* sBDl,
    __half* __restrict__ KVout, int koff, const int* sList, int rem,
    int mbase, int nbase, int lane)
{
    int aColAdd = (lane >> 4) << 3;
    int bg = lane >> 3;
    int bRowAdd = ((bg & 1) << 3) + (lane & 7);
    int bColAdd = (bg >> 1) << 3;
    unsigned aHbase = (unsigned)__cvta_generic_to_shared(sTh + (mbase + (lane & 15)) * PAD_);
    unsigned aLbase = (unsigned)__cvta_generic_to_shared(sTl + (mbase + (lane & 15)) * PAD_);
    int rq = lane >> 2, cq = (lane & 3) * 2;

    #pragma unroll
    for (int r = 0; r < R_; r++) {
        unsigned bHbase = (unsigned)__cvta_generic_to_shared(sBDh + r * BDSZ_);
        unsigned bLbase = (unsigned)__cvta_generic_to_shared(sBDl + r * BDSZ_);
        __half* outR = KVout + (size_t)r * N_ * 256 + koff;
        #pragma unroll
        for (int nt2 = 0; nt2 < 4; nt2++) {
            int head = (nbase >> 4) + nt2;
            unsigned ah[2][4], al[2][4];
            #pragma unroll
            for (int mt = 0; mt < 2; mt++) {
                unsigned offA = (mt * 16 * PAD_ + head * 16 + aColAdd) * 2;
                ldsm4(ah[mt][0], ah[mt][1], ah[mt][2], ah[mt][3], aHbase + offA);
                ldsm4(al[mt][0], al[mt][1], al[mt][2], al[mt][3], aLbase + offA);
            }
            unsigned offB = ((head * 16 + bRowAdd) * BDPAD_ + bColAdd) * 2;
            unsigned bh[4], bl[4];
            ldsm4t(bh[0], bh[1], bh[2], bh[3], bHbase + offB);
            ldsm4t(bl[0], bl[1], bl[2], bl[3], bLbase + offB);

            float acc[2][2][4];
            #pragma unroll
            for (int mt = 0; mt < 2; mt++)
                #pragma unroll
                for (int n8 = 0; n8 < 2; n8++)
                    #pragma unroll
                    for (int q = 0; q < 4; q++) acc[mt][n8][q] = 0.f;
            #pragma unroll
            for (int mt = 0; mt < 2; mt++) {
                mma16816(acc[mt][0], ah[mt], bh);
                mma16816(acc[mt][0], al[mt], bh);
                mma16816(acc[mt][0], ah[mt], bl);
                mma16816(acc[mt][1], ah[mt], bh + 2);
                mma16816(acc[mt][1], al[mt], bh + 2);
                mma16816(acc[mt][1], ah[mt], bl + 2);
            }
            #pragma unroll
            for (int mt = 0; mt < 2; mt++) {
                int rl0 = mbase + mt * 16 + rq;
                #pragma unroll
                for (int n8 = 0; n8 < 2; n8++) {
                    int col = head * 16 + n8 * 8 + cq;
                    float* a = acc[mt][n8];
                    #pragma unroll
                    for (int half = 0; half < 2; half++) {
                        int rl = rl0 + half * 8;
                        if (rl < rem)
                            *(__half2*)(outR + (size_t)sList[rl] * 256 + col) =
                                __floats2half2_rn(a[half * 2], a[half * 2 + 1]);
                    }
                }
            }
        }
    }
}

// QKV stages over the A tile resident in sAh/sAl.
__device__ __forceinline__ void qkv_stages(
    __nv_bfloat16* sAh, __nv_bfloat16* sAl, __nv_bfloat16* sWh, __nv_bfloat16* sWl,
    __nv_bfloat16* sBDh, __nv_bfloat16* sBDl,
    int midx0, int t, const float* Bq, const float* Bk, const float* Bv,
    const __nv_bfloat16* BDhA, const __nv_bfloat16* BDlA,
    const __nv_bfloat16* BDhM, const __nv_bfloat16* BDlM,
    __half* OqH, __half* KVrh,
    const int* sList, int rem, int tid)
{
    int warp = tid >> 5, lane = tid & 31;
    int mbase = (warp & 3) * 32;
    int nbase = (warp >> 2) * 64;
    int rq = lane >> 2, cq = (lane & 3) * 2;

    #pragma unroll
    for (int s = 0; s < 3; s++) {
        if (s > 0) __syncthreads();
        load_w_smem(sWh, sWl, midx0 + s, t, tid);
        __syncthreads();

        float acc[2][8][4];
        #pragma unroll
        for (int i = 0; i < 2; i++)
            #pragma unroll
            for (int j = 0; j < 8; j++)
                #pragma unroll
                for (int q = 0; q < 4; q++) acc[i][j][q] = 0.f;

        mma_tile(acc, sAh, sAl, sWh, sWl, mbase, nbase, lane);

        const float* Bt = (s == 0 ? Bq : s == 1 ? Bk : Bv) + t * D_;

        if (s == 0) {
            #pragma unroll
            for (int mt = 0; mt < 2; mt++) {
                int rl0 = mbase + mt * 16 + rq;
                #pragma unroll
                for (int nt = 0; nt < 8; nt++) {
                    int col = nbase + nt * 8 + cq;
                    float b0 = Bt[col], b1 = Bt[col + 1];
                    float* a = acc[mt][nt];
                    #pragma unroll
                    for (int half = 0; half < 2; half++) {
                        int rl = rl0 + half * 8;
                        if (rl < rem)
                            *(__half2*)(OqH + (size_t)sList[rl] * D_ + col) =
                                __floats2half2_rn(a[half * 2] + b0, a[half * 2 + 1] + b1);
                    }
                }
            }
        } else {
            __syncthreads();   // all warps done reading sW
            #pragma unroll
            for (int mt = 0; mt < 2; mt++) {
                int rl0 = mbase + mt * 16 + rq;
                #pragma unroll
                for (int nt = 0; nt < 8; nt++) {
                    int col = nbase + nt * 8 + cq;
                    float b0 = Bt[col], b1 = Bt[col + 1];
                    float* a = acc[mt][nt];
                    #pragma unroll
                    for (int half = 0; half < 2; half++) {
                        int row = rl0 + half * 8;
                        float v0 = a[half * 2] + b0, v1 = a[half * 2 + 1] + b1;
                        __nv_bfloat16 h0 = __float2bfloat16_rn(v0);
                        __nv_bfloat16 h1 = __float2bfloat16_rn(v1);
                        __nv_bfloat16 l0 = __float2bfloat16_rn(v0 - __bfloat162float(h0));
                        __nv_bfloat16 l1 = __float2bfloat16_rn(v1 - __bfloat162float(h1));
                        *(unsigned*)(sWh + row * PAD_ + col) = pack_bf2(h0, h1);
                        *(unsigned*)(sWl + row * PAD_ + col) = pack_bf2(l0, l1);
                    }
                }
            }
            {
                const uint4* gh = (const uint4*)(s == 1 ? BDhA : BDhM);
                const uint4* gl = (const uint4*)(s == 1 ? BDlA : BDlM);
                uint4* dh = (uint4*)sBDh;
                uint4* dl = (uint4*)sBDl;
                #pragma unroll
                for (int it = 0; it < (R_ * BDSZ_ / 8 + 255) / 256; it++) {
                    int i = it * 256 + tid;
                    if (i < R_ * BDSZ_ / 8) { dh[i] = gh[i]; dl[i] = gl[i]; }
                }
            }
            __syncthreads();
            bd_transform_store(sWh, sWl, sBDh, sBDl, KVrh, (s == 1 ? 0 : 128),
                               sList, rem, mbase, nbase, lane);
        }
    }
}

// ---------------- QKV + relation-transform GEMM ----------------
__global__ void __launch_bounds__(256) k_qkvr_gemm(
    const float* __restrict__ in, int midx0,
    const float* __restrict__ Bq, const float* __restrict__ Bk, const float* __restrict__ Bv,
    const __nv_bfloat16* __restrict__ BDhA, const __nv_bfloat16* __restrict__ BDlA,
    const __nv_bfloat16* __restrict__ BDhM, const __nv_bfloat16* __restrict__ BDlM,
    __half* __restrict__ OqH, __half* __restrict__ KVrh)
{
    int t = blockIdx.y;
    int cnt = g_typeCnt[t];
    int base = blockIdx.x * 128;
    if (base >= cnt) return;
    const int* list = &g_typeList[t][base];
    int rem = cnt - base; if (rem > 128) rem = 128;

    extern __shared__ __nv_bfloat16 sm[];
    __nv_bfloat16* sAh = sm;
    __nv_bfloat16* sAl = sAh + 128 * PAD_;
    __nv_bfloat16* sWh = sAl + 128 * PAD_;
    __nv_bfloat16* sWl = sWh + 128 * PAD_;
    __nv_bfloat16* sBDh = sWl + 128 * PAD_;
    __nv_bfloat16* sBDl = sBDh + R_ * BDSZ_;
    __shared__ int sList[128];

    int tid = threadIdx.x;
    if (tid < 128) sList[tid] = (tid < rem) ? list[tid] : list[0];
    __syncthreads();

    load_a_smem(sAh, sAl, in, sList, 0, tid, nullptr);

    qkv_stages(sAh, sAl, sWh, sWl, sBDh, sBDl, midx0, t, Bq, Bk, Bv,
               BDhA, BDlA, BDhM, BDlM, OqH, KVrh, sList, rem, tid);
}

// ---------------- fused trans + next-layer QKV ----------------
__global__ void __launch_bounds__(256) k_trans_qkvr(
    const float* __restrict__ inA, int midxA,
    const float* __restrict__ BbaseA, float* __restrict__ outA,
    const float* __restrict__ prev, const float* __restrict__ skipv,
    const float* __restrict__ den,
    int midxQ,
    const float* __restrict__ Bq, const float* __restrict__ Bk, const float* __restrict__ Bv,
    const __nv_bfloat16* __restrict__ BDhA, const __nv_bfloat16* __restrict__ BDlA,
    const __nv_bfloat16* __restrict__ BDhM, const __nv_bfloat16* __restrict__ BDlM,
    __half* __restrict__ OqH, __half* __restrict__ KVrh)
{
    int t = blockIdx.y;
    int cnt = g_typeCnt[t];
    int base = blockIdx.x * 128;
    if (base >= cnt) return;
    const int* list = &g_typeList[t][base];
    int rem = cnt - base; if (rem > 128) rem = 128;

    extern __shared__ __nv_bfloat16 sm[];
    __nv_bfloat16* sAh = sm;
    __nv_bfloat16* sAl = sAh + 128 * PAD_;
    __nv_bfloat16* sWh = sAl + 128 * PAD_;
    __nv_bfloat16* sWl = sWh + 128 * PAD_;
    __nv_bfloat16* sBDh = sWl + 128 * PAD_;
    __nv_bfloat16* sBDl = sBDh + R_ * BDSZ_;
    __shared__ int sList[128];

    int tid = threadIdx.x;
    if (tid < 128) sList[tid] = (tid < rem) ? list[tid] : list[0];
    __syncthreads();

    load_a_smem(sAh, sAl, inA, sList, 2, tid, den);
    load_w_smem(sWh, sWl, midxA, t, tid);
    __syncthreads();

    int warp = tid >> 5, lane = tid & 31;
    int mbase = (warp & 3) * 32;
    int nbase = (warp >> 2) * 64;
    int rq = lane >> 2, cq = (lane & 3) * 2;

    float acc[2][8][4];
    #pragma unroll
    for (int i = 0; i < 2; i++)
        #pragma unroll
        for (int j = 0; j < 8; j++)
            #pragma unroll
            for (int q = 0; q < 4; q++) acc[i][j][q] = 0.f;

    mma_tile(acc, sAh, sAl, sWh, sWl, mbase, nbase, lane);
    __syncthreads();   // all warps done reading sAh/sAl

    {
        const float* Bt = BbaseA + t * D_;
        float alpha = 1.f / (1.f + expf(-skipv[t]));
        float beta = 1.f - alpha;
        #pragma unroll
        for (int mt = 0; mt < 2; mt++) {
            int rl0 = mbase + mt * 16 + rq;
            #pragma unroll
            for (int nt = 0; nt < 8; nt++) {
                int col = nbase + nt * 8 + cq;
                float b0 = Bt[col], b1 = Bt[col + 1];
                float* a = acc[mt][nt];
                #pragma unroll
                for (int half = 0; half < 2; half++) {
                    int row = rl0 + half * 8;
                    int grow = sList[row];
                    const float* pp = prev + (size_t)grow * D_ + col;
                    float2 old = *(const float2*)pp;
                    float v0 = alpha * (a[half * 2]     + b0) + beta * old.x;
                    float v1 = alpha * (a[half * 2 + 1] + b1) + beta * old.y;
                    if (row < rem)
                        *(float2*)(outA + (size_t)grow * D_ + col) = make_float2(v0, v1);
                    __nv_bfloat16 h0 = __float2bfloat16_rn(v0);
                    __nv_bfloat16 h1 = __float2bfloat16_rn(v1);
                    __nv_bfloat16 l0 = __float2bfloat16_rn(v0 - __bfloat162float(h0));
                    __nv_bfloat16 l1 = __float2bfloat16_rn(v1 - __bfloat162float(h1));
                    *(unsigned*)(sAh + row * PAD_ + col) = pack_bf2(h0, h1);
                    *(unsigned*)(sAl + row * PAD_ + col) = pack_bf2(l0, l1);
                }
            }
        }
    }
    qkv_stages(sAh, sAl, sWh, sWl, sBDh, sBDl, midxQ, t, Bq, Bk, Bv,
               BDhA, BDlA, BDhM, BDlM, OqH, KVrh, sList, rem, tid);
}

// ---------------- single typed GEMM (adapt / final trans) ----------------
__global__ void __launch_bounds__(256) k_typed_gemm(
    int inop, int outop,
    const float* __restrict__ in, int midx,
    const float* __restrict__ Bbase,
    float* __restrict__ out,
    const float* __restrict__ prev,
    const float* __restrict__ skipv,
    const float* __restrict__ den)
{
    int t = blockIdx.y;
    int cnt = g_typeCnt[t];
    int base = blockIdx.x * 128;
    if (base >= cnt) return;
    const int* list = &g_typeList[t][base];
    int rem = cnt - base; if (rem > 128) rem = 128;

    extern __shared__ __nv_bfloat16 sm[];
    __nv_bfloat16* sAh = sm;
    __nv_bfloat16* sAl = sAh + 128 * PAD_;
    __nv_bfloat16* sWh = sAl + 128 * PAD_;
    __nv_bfloat16* sWl = sWh + 128 * PAD_;
    __shared__ int sList[128];

    int tid = threadIdx.x;
    if (tid < 128) sList[tid] = (tid < rem) ? list[tid] : list[0];
    __syncthreads();

    load_a_smem(sAh, sAl, in, sList, inop, tid, den);
    load_w_smem(sWh, sWl, midx, t, tid);
    __syncthreads();

    int warp = tid >> 5, lane = tid & 31;
    int mbase = (warp & 3) * 32;
    int nbase = (warp >> 2) * 64;

    float acc[2][8][4];
    #pragma unroll
    for (int i = 0; i < 2; i++)
        #pragma unroll
        for (int j = 0; j < 8; j++)
            #pragma unroll
            for (int q = 0; q < 4; q++) acc[i][j][q] = 0.f;

    mma_tile(acc, sAh, sAl, sWh, sWl, mbase, nbase, lane);

    const float* Bt = Bbase + t * D_;
    float alpha = 0.f, beta = 0.f;
    if (outop == 2) { alpha = 1.f / (1.f + expf(-skipv[t])); beta = 1.f - alpha; }

    int rq = lane >> 2, cq = (lane & 3) * 2;
    #pragma unroll
    for (int mt = 0; mt < 2; mt++) {
        int rl0 = mbase + mt * 16 + rq;
        #pragma unroll
        for (int nt = 0; nt < 8; nt++) {
            int col = nbase + nt * 8 + cq;
            float b0 = Bt[col], b1 = Bt[col + 1];
            float* a = acc[mt][nt];
            #pragma unroll
            for (int half = 0; half < 2; half++) {
                int rl = rl0 + half * 8;
                if (rl < rem) {
                    int grow = sList[rl];
                    float v0 = a[half * 2]     + b0;
                    float v1 = a[half * 2 + 1] + b1;
                    if (outop == 1) { v0 = tanhf(v0); v1 = tanhf(v1); }
                    else if (outop == 2) {
                        const float* pp = prev + (size_t)grow * D_ + col;
                        float2 old = *(const float2*)pp;
                        v0 = alpha * v0 + beta * old.x;
                        v1 = alpha * v1 + beta * old.y;
                    }
                    *(float2*)(out + (size_t)grow * D_ + col) = make_float2(v0, v1);
                }
            }
        }
    }
}

// ---------------- fused edge pass (2x unrolled for MLP) ----------------
__global__ void __launch_bounds__(256) k_edgeAC(const __half* __restrict__ tabKV,
                                                const float* __restrict__ relPri,
                                                float* __restrict__ aggr,
                                                float* __restrict__ den) {
    int r = blockIdx.y;
    int lo = g_bOff[r * NPB_], hi = g_bOff[(r + 1) * NPB_];
    int lane = threadIdx.x & 31;
    int h = lane & 7, esub = lane >> 3;
    int warp = blockIdx.x * (blockDim.x >> 5) + (threadIdx.x >> 5);
    int nwarp = gridDim.x * (blockDim.x >> 5);
    const __half* KVr = g_KVrh + (size_t)r * N_ * 256;
    const __half* tabR = tabKV + (size_t)r * T_ * ML_ * 256;

    for (int eb = lo + warp * 8; eb < hi; eb += nwarp * 8) {
        // two batches of 4 edges; all gathers front-issued for MLP
        int p0 = eb + esub;
        int p1 = eb + 4 + esub;
        bool v0ok = p0 < hi, v1ok = p1 < hi;
        int pp0 = v0ok ? p0 : lo;
        int pp1 = v1ok ? p1 : lo;
        int s0 = g_eS[pp0], t0 = g_eT[pp0], m0 = g_eMeta[pp0];
        int s1 = g_eS[pp1], t1 = g_eT[pp1], m1 = g_eMeta[pp1];
        int st0 = m0 & 3, tt0 = (m0 >> 2) & 3, tm0 = m0 >> 4;
        int st1 = m1 & 3, tt1 = (m1 >> 2) & 3, tm1 = m1 >> 4;

        const __half* kvb0 = KVr + (size_t)s0 * 256 + h * 16;
        const __half* kvb1 = KVr + (size_t)s1 * 256 + h * 16;
        const __half* tbb0 = tabR + (size_t)(st0 * ML_ + tm0) * 256 + h * 16;
        const __half* tbb1 = tabR + (size_t)(st1 * ML_ + tm1) * 256 + h * 16;

        // front-issue ALL loads (K, V, tabs, Q for both batches)
        __half2 kh0[8], qh0[8], th0[8], vh0[8], tvh0[8];
        __half2 kh1[8], qh1[8], th1[8], vh1[8], tvh1[8];
        {
            const uint4* kp0 = (const uint4*)kvb0;
            const uint4* kp1 = (const uint4*)kvb1;
            const uint4* vp0 = (const uint4*)(kvb0 + 128);
            const uint4* vp1 = (const uint4*)(kvb1 + 128);
            const uint4* qp0 = (const uint4*)(g_Qh + (size_t)t0 * D_ + h * 16);
            const uint4* qp1 = (const uint4*)(g_Qh + (size_t)t1 * D_ + h * 16);
            const uint4* tp0 = (const uint4*)tbb0;
            const uint4* tp1 = (const uint4*)tbb1;
            const uint4* tv0 = (const uint4*)(tbb0 + 128);
            const uint4* tv1 = (const uint4*)(tbb1 + 128);
            *(uint4*)(kh0) = kp0[0]; *(uint4*)(kh0 + 4) = kp0[1];
            *(uint4*)(kh1) = kp1[0]; *(uint4*)(kh1 + 4) = kp1[1];
            *(uint4*)(vh0) = vp0[0]; *(uint4*)(vh0 + 4) = vp0[1];
            *(uint4*)(vh1) = vp1[0]; *(uint4*)(vh1 + 4) = vp1[1];
            *(uint4*)(qh0) = qp0[0]; *(uint4*)(qh0 + 4) = qp0[1];
            *(uint4*)(qh1) = qp1[0]; *(uint4*)(qh1 + 4) = qp1[1];
            *(uint4*)(th0) = tp0[0]; *(uint4*)(th0 + 4) = tp0[1];
            *(uint4*)(th1) = tp1[0]; *(uint4*)(th1 + 4) = tp1[1];
            *(uint4*)(tvh0) = tv0[0]; *(uint4*)(tvh0 + 4) = tv0[1];
            *(uint4*)(tvh1) = tv1[0]; *(uint4*)(tvh1 + 4) = tv1[1];
        }

        float sc0 = 0.f, sc1 = 0.f;
        #pragma unroll
        for (int i = 0; i < 8; i++) {
            float2 kf0 = __half22float2(kh0[i]), qf0 = __half22float2(qh0[i]);
            float2 tf0 = __half22float2(th0[i]);
            sc0 += qf0.x * (kf0.x + tf0.x) + qf0.y * (kf0.y + tf0.y);
            float2 kf1 = __half22float2(kh1[i]), qf1 = __half22float2(qh1[i]);
            float2 tf1 = __half22float2(th1[i]);
            sc1 += qf1.x * (kf1.x + tf1.x) + qf1.y * (kf1.y + tf1.y);
        }
        float pri0 = relPri[((tt0 * R_ + r) * T_ + st0) * H_ + h];
        float pri1 = relPri[((tt1 * R_ + r) * T_ + st1) * H_ + h];
        // scores are O(1): exp without max-subtraction cannot overflow fp32;
        // softmax is shift-invariant so result is exact.
        float ex0 = expf(sc0 * pri0 * 0.25f);
        float ex1 = expf(sc1 * pri1 * 0.25f);

        if (v0ok) {
            atomicAdd(&den[t0 * H_ + h], ex0);
            float* op = aggr + (size_t)t0 * D_ + h * 16;
            #pragma unroll
            for (int i = 0; i < 4; i++) {
                float2 a = __half22float2(vh0[2 * i]);
                float2 b = __half22float2(vh0[2 * i + 1]);
                float2 ta = __half22float2(tvh0[2 * i]);
                float2 tb = __half22float2(tvh0[2 * i + 1]);
                red_add_v4(op + i * 4,
                           (a.x + ta.x) * ex0, (a.y + ta.y) * ex0,
                           (b.x + tb.x) * ex0, (b.y + tb.y) * ex0);
            }
        }
        if (v1ok) {
            atomicAdd(&den[t1 * H_ + h], ex1);
            float* op = aggr + (size_t)t1 * D_ + h * 16;
            #pragma unroll
            for (int i = 0; i < 4; i++) {
                float2 a = __half22float2(vh1[2 * i]);
                float2 b = __half22float2(vh1[2 * i + 1]);
                float2 ta = __half22float2(tvh1[2 * i]);
                float2 tb = __half22float2(tvh1[2 * i + 1]);
                red_add_v4(op + i * 4,
                           (a.x + ta.x) * ex1, (a.y + ta.y) * ex1,
                           (b.x + tb.x) * ex1, (b.y + tb.y) * ex1);
            }
        }
    }
}

// ---------------- launch ----------------
static cudaStream_t s1 = nullptr, s2 = nullptr, s3 = nullptr;
static cudaEvent_t evF = nullptr, evBuck = nullptr, evInit = nullptr;
static cudaEvent_t evTab0 = nullptr, evTab1 = nullptr, evW0 = nullptr, evW1 = nullptr;

extern "C" void kernel_launch(void* const* d_in, const int* in_sizes, int n_in,
                              void* d_out, int out_size) {
    const float* node_feature = (const float*)d_in[0];
    const int*   node_type    = (const int*)d_in[1];
    const int*   edge_index   = (const int*)d_in[2];
    const int*   edge_type    = (const int*)d_in[3];
    const int*   edge_time    = (const int*)d_in[4];
    const float* adapt_w      = (const float*)d_in[5];
    const float* adapt_b      = (const float*)d_in[6];
    const float* Wk           = (const float*)d_in[7];
    const float* bk           = (const float*)d_in[8];
    const float* Wq           = (const float*)d_in[9];
    const float* bq           = (const float*)d_in[10];
    const float* Wv           = (const float*)d_in[11];
    const float* bv           = (const float*)d_in[12];
    const float* Wa           = (const float*)d_in[13];
    const float* ba           = (const float*)d_in[14];
    const float* rel_pri      = (const float*)d_in[15];
    const float* rel_att      = (const float*)d_in[16];
    const float* rel_msg      = (const float*)d_in[17];
    const float* skip         = (const float*)d_in[18];
    const float* rte_w        = (const float*)d_in[19];
    const float* rte_b        = (const float*)d_in[20];

    const int* src = edge_index;
    const int* tgt = edge_index + E_;

    if (!s1) {
        cudaStreamCreateWithFlags(&s1, cudaStreamNonBlocking);
        cudaStreamCreateWithFlags(&s2, cudaStreamNonBlocking);
        cudaStreamCreateWithFlags(&s3, cudaStreamNonBlocking);
        cudaEventCreateWithFlags(&evF, cudaEventDisableTiming);
        cudaEventCreateWithFlags(&evBuck, cudaEventDisableTiming);
        cudaEventCreateWithFlags(&evInit, cudaEventDisableTiming);
        cudaEventCreateWithFlags(&evTab0, cudaEventDisableTiming);
        cudaEventCreateWithFlags(&evTab1, cudaEventDisableTiming);
        cudaEventCreateWithFlags(&evW0, cudaEventDisableTiming);
        cudaEventCreateWithFlags(&evW1, cudaEventDisableTiming);
        cudaFuncSetAttribute(k_typed_gemm, cudaFuncAttributeMaxDynamicSharedMemorySize, GEMM_SMEM);
        cudaFuncSetAttribute(k_qkvr_gemm, cudaFuncAttributeMaxDynamicSharedMemorySize, QKVR_SMEM);
        cudaFuncSetAttribute(k_trans_qkvr, cudaFuncAttributeMaxDynamicSharedMemorySize, QKVR_SMEM);
    }

    float *px, *pa0, *pa1, *pd0, *pd1;
    __half *pQh, *pKVrh, *ptKV0;
    __nv_bfloat16 *pBDh, *pBDl;
    cudaGetSymbolAddress((void**)&px, g_x);
    cudaGetSymbolAddress((void**)&pQh, g_Qh);
    cudaGetSymbolAddress((void**)&pa0, g_aggr);
    pa1 = pa0 + TD_;
    cudaGetSymbolAddress((void**)&pd0, g_den);
    pd1 = pd0 + N_ * H_;
    cudaGetSymbolAddress((void**)&pKVrh, g_KVrh);
    cudaGetSymbolAddress((void**)&ptKV0, g_tabKVh);
    cudaGetSymbolAddress((void**)&pBDh, g_BDh);
    cudaGetSymbolAddress((void**)&pBDl, g_BDl);
    const size_t TABSTRIDE = (size_t)R_ * T_ * ML_ * 256;

    dim3 ggrid((N_ + 127) / 128, T_);
    dim3 egrid(128, R_);
    const int WSPLIT_GRID = (T_ * D_ * D_ + 255) / 256;
    size_t woff1 = (size_t)T_ * 128 * 128;

    // fork all three side streams from the capture origin
    cudaEventRecord(evF, 0);
    cudaStreamWaitEvent(s1, evF, 0);
    cudaStreamWaitEvent(s2, evF, 0);
    cudaStreamWaitEvent(s3, evF, 0);

    // s1: edge bucketing + layer-buffer zeroing
    k_init_bkt<<<(NB_ + 255) / 256, 256, 0, s1>>>();
    k_count_b<<<(E_ + 255) / 256, 256, 0, s1>>>(tgt, edge_type);
    k_scan_b<<<1, 1024, 0, s1>>>();
    k_scatter_b<<<(E_ + 255) / 256, 256, 0, s1>>>(src, tgt, edge_type, edge_time, node_type);
    cudaEventRecord(evBuck, s1);
    k_init_layer<<<2048, 256, 0, s1>>>();   // zero both layers' aggr/den
    cudaEventRecord(evInit, s1);

    // s2: RTE tables (layer 0 then layer 1)
    k_rte_tab<<<ML_, 128, 0, s2>>>();
    k_rte_proj<<<ML_, 128, 0, s2>>>(rte_w, rte_b);
    k_tables<<<T_ * ML_, 128, 0, s2>>>(Wk, Wv, rel_att, rel_msg, 0);
    cudaEventRecord(evTab0, s2);
    k_rte_proj<<<ML_, 128, 0, s2>>>(rte_w + (size_t)256 * 128, rte_b + 128);
    k_tables<<<T_ * ML_, 128, 0, s2>>>(Wk + woff1, Wv + woff1,
                                       rel_att + (size_t)R_ * H_ * 256,
                                       rel_msg + (size_t)R_ * H_ * 256, 1);
    cudaEventRecord(evTab1, s2);

    // s3: weight splits (layer-0 QKV first, then the rest)
    k_relsplit<<<(2 * 2 * R_ * H_ * 256 + 255) / 256, 256, 0, s3>>>(rel_att, rel_msg);
    k_wsplit<<<WSPLIT_GRID, 256, 0, s3>>>(Wq, 1);
    k_wsplit<<<WSPLIT_GRID, 256, 0, s3>>>(Wk, 2);
    k_wsplit<<<WSPLIT_GRID, 256, 0, s3>>>(Wv, 3);
    cudaEventRecord(evW0, s3);
    k_wsplit<<<WSPLIT_GRID, 256, 0, s3>>>(Wa, 4);
    k_wsplit<<<WSPLIT_GRID, 256, 0, s3>>>(Wq + woff1, 5);
    k_wsplit<<<WSPLIT_GRID, 256, 0, s3>>>(Wk + woff1, 6);
    k_wsplit<<<WSPLIT_GRID, 256, 0, s3>>>(Wv + woff1, 7);
    k_wsplit<<<WSPLIT_GRID, 256, 0, s3>>>(Wa + woff1, 8);
    cudaEventRecord(evW1, s3);

    // main: type buckets + adapt GEMM
    k_init_type<<<1, 32>>>();
    k_build_type<<<(N_ + 255) / 256, 256>>>(node_type);
    k_wsplit<<<WSPLIT_GRID, 256>>>(adapt_w, 0);
    k_typed_gemm<<<ggrid, 256, GEMM_SMEM>>>(0, 1, node_feature, 0, adapt_b, px, px, nullptr, nullptr);

    cudaStreamWaitEvent(0, evW0, 0);   // Wq/Wk/Wv(l0) + BD splits ready
    k_qkvr_gemm<<<ggrid, 256, QKVR_SMEM>>>(
        px, 1, bq, bk, bv,
        pBDh + 0 * R_ * BDSZ_, pBDl + 0 * R_ * BDSZ_,
        pBDh + 1 * R_ * BDSZ_, pBDl + 1 * R_ * BDSZ_,
        pQh, pKVrh);

    cudaStreamWaitEvent(0, evBuck, 0);
    cudaStreamWaitEvent(0, evTab0, 0);
    cudaStreamWaitEvent(0, evInit, 0);
    k_edgeAC<<<egrid, 256>>>(ptKV0, rel_pri, pa0, pd0);

    cudaStreamWaitEvent(0, evW1, 0);   // Wa(l0) + l1 weights ready
    k_trans_qkvr<<<ggrid, 256, QKVR_SMEM>>>(
        pa0, 4, ba, px, px, skip, pd0,
        5, bq + T_ * 128, bk + T_ * 128, bv + T_ * 128,
        pBDh + 2 * R_ * BDSZ_, pBDl + 2 * R_ * BDSZ_,
        pBDh + 3 * R_ * BDSZ_, pBDl + 3 * R_ * BDSZ_,
        pQh, pKVrh);

    cudaStreamWaitEvent(0, evTab1, 0);
    k_edgeAC<<<egrid, 256>>>(ptKV0 + TABSTRIDE, rel_pri + (size_t)T_ * R_ * T_ * H_, pa1, pd1);

    // final trans -> d_out
    k_typed_gemm<<<ggrid, 256, GEMM_SMEM>>>(2, 2, pa1, 8, ba + T_ * 128,
                                            (float*)d_out, px, skip + T_, pd1);
}

// round 14
// speedup vs baseline: 1.0067x; 1.0067x over previous
#include <cuda_runtime.h>
#include <cuda_bf16.h>
#include <cuda_fp16.h>
#include <math.h>

#define N_ 100000
#define E_ 500000
#define D_ 128
#define T_ 3
#define R_ 4
#define H_ 8
#define ML_ 240
#define TD_ ((size_t)N_*(size_t)D_)
#define PAD_ 136
#define BDPAD_ 24
#define BDSZ_ (H_*16*BDPAD_)
#define GEMM_SMEM (4 * 128 * PAD_ * 2)
#define QKVR_SMEM ((4 * 128 * PAD_ + 2 * R_ * BDSZ_) * 2)
#define NMAT_ 9
#define NPB_ ((N_ + 127) / 128)
#define NB_  (R_ * NPB_)

__device__ float g_x[TD_];
__device__ __half g_Qh[TD_];
__device__ float g_aggr[2][TD_];          // per-layer unnormalized U
__device__ float g_den[2][N_*H_];
__device__ __half g_KVrh[(size_t)R_*N_*2*D_];   // K at +0, V at +128 (per node)
__device__ float g_rte_tab[ML_*2*D_];
__device__ float g_rte_proj[ML_*D_];
__device__ __half g_tabKVh[2][(size_t)R_*T_*ML_*2*D_];  // K at +0, V at +128
__device__ __nv_bfloat16 g_Wh[(size_t)NMAT_*T_*D_*D_];
__device__ __nv_bfloat16 g_Wl[(size_t)NMAT_*T_*D_*D_];
__device__ __nv_bfloat16 g_BDh[2*2*R_*BDSZ_];
__device__ __nv_bfloat16 g_BDl[2*2*R_*BDSZ_];
__device__ int   g_typeList[T_][N_];
__device__ int   g_typeCnt[T_];
__device__ int   g_bCnt[NB_];
__device__ int   g_bOff[NB_+1];
__device__ int   g_bFill[NB_];
__device__ int   g_eS[E_];
__device__ int   g_eT[E_];
__device__ int   g_eMeta[E_];   // st | tt<<2 | time<<4

__device__ __forceinline__ float gelu_f(float x) { return x * normcdff(x); }

__device__ __forceinline__ void red_add_v4(float* p, float a, float b, float c, float d) {
    asm volatile("red.global.add.v4.f32 [%0], {%1,%2,%3,%4};"
                 :: "l"(p), "f"(a), "f"(b), "f"(c), "f"(d) : "memory");
}

// ---------------- mma helpers ----------------
__device__ __forceinline__ void ldsm4(unsigned& r0, unsigned& r1, unsigned& r2, unsigned& r3,
                                      unsigned addr) {
    asm volatile("ldmatrix.sync.aligned.m8n8.x4.shared.b16 {%0,%1,%2,%3}, [%4];"
                 : "=r"(r0), "=r"(r1), "=r"(r2), "=r"(r3) : "r"(addr));
}
__device__ __forceinline__ void ldsm4t(unsigned& r0, unsigned& r1, unsigned& r2, unsigned& r3,
                                       unsigned addr) {
    asm volatile("ldmatrix.sync.aligned.m8n8.x4.trans.shared.b16 {%0,%1,%2,%3}, [%4];"
                 : "=r"(r0), "=r"(r1), "=r"(r2), "=r"(r3) : "r"(addr));
}
__device__ __forceinline__ void mma16816(float* d, const unsigned* a, const unsigned* b) {
    asm volatile("mma.sync.aligned.m16n8k16.row.col.f32.bf16.bf16.f32 "
                 "{%0,%1,%2,%3}, {%4,%5,%6,%7}, {%8,%9}, {%0,%1,%2,%3};"
                 : "+f"(d[0]), "+f"(d[1]), "+f"(d[2]), "+f"(d[3])
                 : "r"(a[0]), "r"(a[1]), "r"(a[2]), "r"(a[3]), "r"(b[0]), "r"(b[1]));
}
__device__ __forceinline__ unsigned pack_bf2(__nv_bfloat16 a, __nv_bfloat16 b) {
    __nv_bfloat162 p(a, b);
    return *reinterpret_cast<unsigned*>(&p);
}

// ---------------- precompute kernels ----------------
__global__ void k_rte_tab() {
    int pos = blockIdx.x;
    int i   = threadIdx.x;
    const float s = 0.08838834764831845f;
    float div;
    if (i >= 5) div = 0.f;   // fp32 10000^ar overflow -> inf -> 0
    else {
        float pf = (float)pow(10000.0, (double)(2 * i));
        div = 1.0f / ((pf / 128.0f) / 2.0f);
    }
    float ang = (float)pos * div;
    double a = (double)ang;
    g_rte_tab[pos * 256 + 2 * i]     = (float)sin(a) * s;
    g_rte_tab[pos * 256 + 2 * i + 1] = (float)cos(a) * s;
}

__global__ void k_rte_proj(const float* __restrict__ w, const float* __restrict__ b) {
    int time = blockIdx.x;
    int d    = threadIdx.x;
    float acc = b[d];
    const float* tr = g_rte_tab + time * 256;
    for (int c = 0; c < 256; c++) acc += tr[c] * w[c * 128 + d];
    g_rte_proj[time * 128 + d] = acc;
}

__global__ void k_tables(const float* __restrict__ Wk, const float* __restrict__ Wv,
                         const float* __restrict__ relAtt, const float* __restrict__ relMsg,
                         int l) {
    __shared__ float sK[128], sV[128];
    int id = blockIdx.x;
    int d  = threadIdx.x;
    int t = id / ML_, time = id % ML_;
    const float* pr = g_rte_proj + time * 128;
    const float* wk = Wk + (size_t)t * 128 * 128;
    const float* wv = Wv + (size_t)t * 128 * 128;
    float aK = 0.f, aV = 0.f;
    for (int k = 0; k < 128; k++) {
        float p = pr[k];
        aK += p * wk[k * 128 + d];
        aV += p * wv[k * 128 + d];
    }
    sK[d] = aK; sV[d] = aV;
    __syncthreads();
    int h = d >> 4, dk = d & 15;
    size_t rowoff = (size_t)(t * ML_ + time) * 256 + d;
    for (int r = 0; r < R_; r++) {
        const float* A = relAtt + ((size_t)r * H_ + h) * 256;
        const float* M = relMsg + ((size_t)r * H_ + h) * 256;
        float k2 = 0.f, v2 = 0.f;
        #pragma unroll
        for (int j = 0; j < 16; j++) {
            k2 += sK[h * 16 + j] * A[j * 16 + dk];
            v2 += sV[h * 16 + j] * M[j * 16 + dk];
        }
        g_tabKVh[l][(size_t)r * T_ * ML_ * 256 + rowoff]       = __float2half_rn(k2);
        g_tabKVh[l][(size_t)r * T_ * ML_ * 256 + rowoff + 128] = __float2half_rn(v2);
    }
}

__global__ void k_wsplit(const float* __restrict__ src, int midx) {
    int i = blockIdx.x * blockDim.x + threadIdx.x;
    int n = T_ * D_ * D_;
    if (i >= n) return;
    size_t off = (size_t)midx * n + i;
    float v = src[i];
    __nv_bfloat16 h = __float2bfloat16_rn(v);
    g_Wh[off] = h;
    g_Wl[off] = __float2bfloat16_rn(v - __bfloat162float(h));
}

__global__ void k_relsplit(const float* __restrict__ relAtt, const float* __restrict__ relMsg) {
    int idx = blockIdx.x * blockDim.x + threadIdx.x;
    if (idx >= 2 * 2 * R_ * H_ * 256) return;
    int c = idx & 15, k = (idx >> 4) & 15, h = (idx >> 8) & 7;
    int r = (idx >> 11) & 3, w = (idx >> 13) & 1, l = idx >> 14;
    const float* src = w ? relMsg : relAtt;
    float v = src[(((size_t)l * R_ + r) * H_ + h) * 256 + k * 16 + c];
    __nv_bfloat16 hi = __float2bfloat16_rn(v);
    size_t dst = (size_t)(((l * 2 + w) * R_ + r)) * BDSZ_ + (h * 16 + k) * BDPAD_ + c;
    g_BDh[dst] = hi;
    g_BDl[dst] = __float2bfloat16_rn(v - __bfloat162float(hi));
}

// ---------------- bucketing ----------------
__global__ void k_init_bkt() {
    int i = blockIdx.x * blockDim.x + threadIdx.x;
    if (i < NB_) { g_bCnt[i] = 0; g_bFill[i] = 0; }
}

__global__ void k_init_type() {
    if (threadIdx.x < T_) g_typeCnt[threadIdx.x] = 0;
}

__global__ void k_build_type(const int* __restrict__ nt) {
    __shared__ int c[T_];
    __shared__ int base[T_];
    int tid = threadIdx.x;
    if (tid < T_) c[tid] = 0;
    __syncthreads();
    int i = blockIdx.x * blockDim.x + tid;
    int t = -1, rank = 0;
    if (i < N_) { t = nt[i]; rank = atomicAdd(&c[t], 1); }
    __syncthreads();
    if (tid < T_) base[tid] = c[tid] ? atomicAdd(&g_typeCnt[tid], c[tid]) : 0;
    __syncthreads();
    if (i < N_) g_typeList[t][base[t] + rank] = i;
}

__global__ void k_count_b(const int* __restrict__ tgt, const int* __restrict__ et) {
    int i = blockIdx.x * blockDim.x + threadIdx.x;
    if (i < E_) atomicAdd(&g_bCnt[et[i] * NPB_ + (tgt[i] >> 7)], 1);
}

__global__ void __launch_bounds__(1024) k_scan_b() {
    __shared__ int wsum[32];
    int tid = threadIdx.x;
    int v[4], s = 0;
    #pragma unroll
    for (int i = 0; i < 4; i++) {
        int idx = tid * 4 + i;
        v[i] = (idx < NB_) ? g_bCnt[idx] : 0;
        s += v[i];
    }
    int lane = tid & 31, w = tid >> 5;
    int incl = s;
    #pragma unroll
    for (int d = 1; d < 32; d <<= 1) {
        int o = __shfl_up_sync(0xffffffffu, incl, d);
        if (lane >= d) incl += o;
    }
    if (lane == 31) wsum[w] = incl;
    __syncthreads();
    if (w == 0) {
        int x = (lane < 32) ? wsum[lane] : 0;
        int in2 = x;
        #pragma unroll
        for (int d = 1; d < 32; d <<= 1) {
            int o = __shfl_up_sync(0xffffffffu, in2, d);
            if (lane >= d) in2 += o;
        }
        wsum[lane] = in2 - x;
    }
    __syncthreads();
    int excl = wsum[w] + incl - s;
    #pragma unroll
    for (int i = 0; i < 4; i++) {
        int idx = tid * 4 + i;
        if (idx < NB_) g_bOff[idx] = excl;
        excl += v[i];
    }
    if (tid == 1023) g_bOff[NB_] = E_;
}

__global__ void k_scatter_b(const int* __restrict__ src, const int* __restrict__ tgt,
                            const int* __restrict__ et, const int* __restrict__ etm,
                            const int* __restrict__ nt) {
    int e = blockIdx.x * blockDim.x + threadIdx.x;
    if (e < E_) {
        int t = tgt[e];
        int key = et[e] * NPB_ + (t >> 7);
        int p = g_bOff[key] + atomicAdd(&g_bFill[key], 1);
        int s = src[e];
        g_eS[p] = s;
        g_eT[p] = t;
        g_eMeta[p] = nt[s] | (nt[t] << 2) | (etm[e] << 4);
    }
}

__global__ void k_init_layer() {
    size_t stride = (size_t)gridDim.x * blockDim.x;
    size_t i0 = (size_t)blockIdx.x * blockDim.x + threadIdx.x;
    for (size_t i = i0; i < 2 * (size_t)N_ * H_; i += stride) g_den[0][i] = 0.f;
    for (size_t i = i0; i < 2 * TD_; i += stride) g_aggr[0][i] = 0.f;
}

// ---------------- GEMM building blocks ----------------
__device__ __forceinline__ void load_w_smem(__nv_bfloat16* sWh, __nv_bfloat16* sWl,
                                            int midx, int t, int tid) {
    size_t base = ((size_t)midx * T_ + t) * D_ * D_;
    const uint4* wh4 = (const uint4*)(g_Wh + base);
    const uint4* wl4 = (const uint4*)(g_Wl + base);
    #pragma unroll
    for (int it = 0; it < 8; it++) {
        int idx = it * 256 + tid;
        int row = idx >> 4;
        int col = (idx & 15) * 8;
        *(uint4*)(sWh + row * PAD_ + col) = wh4[idx];
        *(uint4*)(sWl + row * PAD_ + col) = wl4[idx];
    }
}

__device__ __forceinline__ void cvt_store(__nv_bfloat16* sAh, __nv_bfloat16* sAl,
                                          int row, int col, float4 v) {
    __nv_bfloat16 h0 = __float2bfloat16_rn(v.x), h1 = __float2bfloat16_rn(v.y);
    __nv_bfloat16 h2 = __float2bfloat16_rn(v.z), h3 = __float2bfloat16_rn(v.w);
    __nv_bfloat16 l0 = __float2bfloat16_rn(v.x - __bfloat162float(h0));
    __nv_bfloat16 l1 = __float2bfloat16_rn(v.y - __bfloat162float(h1));
    __nv_bfloat16 l2 = __float2bfloat16_rn(v.z - __bfloat162float(h2));
    __nv_bfloat16 l3 = __float2bfloat16_rn(v.w - __bfloat162float(h3));
    *(uint2*)(sAh + row * PAD_ + col) = make_uint2(pack_bf2(h0, h1), pack_bf2(h2, h3));
    *(uint2*)(sAl + row * PAD_ + col) = make_uint2(pack_bf2(l0, l1), pack_bf2(l2, l3));
}

// inop: 0=none, 1=gelu(v), 2=gelu(v/den)
__device__ __forceinline__ void load_a_smem(__nv_bfloat16* sAh, __nv_bfloat16* sAl,
                                            const float* __restrict__ in,
                                            const int* sList, int inop, int tid,
                                            const float* __restrict__ den) {
    #pragma unroll
    for (int it = 0; it < 16; it++) {
        int idx = it * 256 + tid;
        int row = idx >> 5;
        int col = (idx & 31) << 2;
        int grow = sList[row];
        float4 v = *(const float4*)(in + (size_t)grow * D_ + col);
        if (inop == 1) {
            v.x = gelu_f(v.x); v.y = gelu_f(v.y); v.z = gelu_f(v.z); v.w = gelu_f(v.w);
        } else if (inop == 2) {
            float dv = den[grow * H_ + (col >> 4)];
            float inv = dv > 0.f ? 1.f / dv : 0.f;
            v.x = gelu_f(v.x * inv); v.y = gelu_f(v.y * inv);
            v.z = gelu_f(v.z * inv); v.w = gelu_f(v.w * inv);
        }
        cvt_store(sAh, sAl, row, col, v);
    }
}

__device__ __forceinline__ void mma_tile(float (&acc)[2][8][4],
                                         const __nv_bfloat16* sAh, const __nv_bfloat16* sAl,
                                         const __nv_bfloat16* sWh, const __nv_bfloat16* sWl,
                                         int mbase, int nbase, int lane) {
    int aRow = mbase + (lane & 15);
    int aColAdd = (lane >> 4) << 3;
    int bg = lane >> 3;
    int bRowAdd = ((bg & 1) << 3) + (lane & 7);
    int bColAdd = (bg >> 1) << 3;

    unsigned aHbase = (unsigned)__cvta_generic_to_shared(sAh + aRow * PAD_);
    unsigned aLbase = (unsigned)__cvta_generic_to_shared(sAl + aRow * PAD_);
    unsigned wHbase = (unsigned)__cvta_generic_to_shared(sWh);
    unsigned wLbase = (unsigned)__cvta_generic_to_shared(sWl);

    #pragma unroll
    for (int kc = 0; kc < 8; kc++) {
        int k0 = kc * 16;
        unsigned ah[2][4], al[2][4];
        #pragma unroll
        for (int mt = 0; mt < 2; mt++) {
            unsigned off = (mt * 16 * PAD_ + k0 + aColAdd) * 2;
            ldsm4(ah[mt][0], ah[mt][1], ah[mt][2], ah[mt][3], aHbase + off);
            ldsm4(al[mt][0], al[mt][1], al[mt][2], al[mt][3], aLbase + off);
        }
        #pragma unroll
        for (int nt2 = 0; nt2 < 4; nt2++) {
            int nb = nbase + nt2 * 16;
            unsigned off = ((k0 + bRowAdd) * PAD_ + nb + bColAdd) * 2;
            unsigned bh[4], bl[4];
            ldsm4t(bh[0], bh[1], bh[2], bh[3], wHbase + off);
            ldsm4t(bl[0], bl[1], bl[2], bl[3], wLbase + off);
            #pragma unroll
            for (int mt = 0; mt < 2; mt++) {
                mma16816(acc[mt][nt2 * 2],     ah[mt], bh);
                mma16816(acc[mt][nt2 * 2],     al[mt], bh);
                mma16816(acc[mt][nt2 * 2],     ah[mt], bl);
                mma16816(acc[mt][nt2 * 2 + 1], ah[mt], bh + 2);
                mma16816(acc[mt][nt2 * 2 + 1], al[mt], bh + 2);
                mma16816(acc[mt][nt2 * 2 + 1], ah[mt], bl + 2);
            }
        }
    }
}

// block-diag relation transform of tile in sTh/sTl; scatter fp16 to
// KVout[r][node][koff + 0..127] (interleaved K/V layout, node stride 256).
__device__ __forceinline__ void bd_transform_store(
    const __nv_bfloat16* sTh, const __nv_bfloat16* sTl,
    const __nv_bfloat16* sBDh, const __nv_bfloat16* sBDl,
    __half* __restrict__ KVout, int koff, const int* sList, int rem,
    int mbase, int nbase, int lane)
{
    int aColAdd = (lane >> 4) << 3;
    int bg = lane >> 3;
    int bRowAdd = ((bg & 1) << 3) + (lane & 7);
    int bColAdd = (bg >> 1) << 3;
    unsigned aHbase = (unsigned)__cvta_generic_to_shared(sTh + (mbase + (lane & 15)) * PAD_);
    unsigned aLbase = (unsigned)__cvta_generic_to_shared(sTl + (mbase + (lane & 15)) * PAD_);
    int rq = lane >> 2, cq = (lane & 3) * 2;

    #pragma unroll
    for (int r = 0; r < R_; r++) {
        unsigned bHbase = (unsigned)__cvta_generic_to_shared(sBDh + r * BDSZ_);
        unsigned bLbase = (unsigned)__cvta_generic_to_shared(sBDl + r * BDSZ_);
        __half* outR = KVout + (size_t)r * N_ * 256 + koff;
        #pragma unroll
        for (int nt2 = 0; nt2 < 4; nt2++) {
            int head = (nbase >> 4) + nt2;
            unsigned ah[2][4], al[2][4];
            #pragma unroll
            for (int mt = 0; mt < 2; mt++) {
                unsigned offA = (mt * 16 * PAD_ + head * 16 + aColAdd) * 2;
                ldsm4(ah[mt][0], ah[mt][1], ah[mt][2], ah[mt][3], aHbase + offA);
                ldsm4(al[mt][0], al[mt][1], al[mt][2], al[mt][3], aLbase + offA);
            }
            unsigned offB = ((head * 16 + bRowAdd) * BDPAD_ + bColAdd) * 2;
            unsigned bh[4], bl[4];
            ldsm4t(bh[0], bh[1], bh[2], bh[3], bHbase + offB);
            ldsm4t(bl[0], bl[1], bl[2], bl[3], bLbase + offB);

            float acc[2][2][4];
            #pragma unroll
            for (int mt = 0; mt < 2; mt++)
                #pragma unroll
                for (int n8 = 0; n8 < 2; n8++)
                    #pragma unroll
                    for (int q = 0; q < 4; q++) acc[mt][n8][q] = 0.f;
            #pragma unroll
            for (int mt = 0; mt < 2; mt++) {
                mma16816(acc[mt][0], ah[mt], bh);
                mma16816(acc[mt][0], al[mt], bh);
                mma16816(acc[mt][0], ah[mt], bl);
                mma16816(acc[mt][1], ah[mt], bh + 2);
                mma16816(acc[mt][1], al[mt], bh + 2);
                mma16816(acc[mt][1], ah[mt], bl + 2);
            }
            #pragma unroll
            for (int mt = 0; mt < 2; mt++) {
                int rl0 = mbase + mt * 16 + rq;
                #pragma unroll
                for (int n8 = 0; n8 < 2; n8++) {
                    int col = head * 16 + n8 * 8 + cq;
                    float* a = acc[mt][n8];
                    #pragma unroll
                    for (int half = 0; half < 2; half++) {
                        int rl = rl0 + half * 8;
                        if (rl < rem)
                            *(__half2*)(outR + (size_t)sList[rl] * 256 + col) =
                                __floats2half2_rn(a[half * 2], a[half * 2 + 1]);
                    }
                }
            }
        }
    }
}

// QKV stages over the A tile resident in sAh/sAl.
__device__ __forceinline__ void qkv_stages(
    __nv_bfloat16* sAh, __nv_bfloat16* sAl, __nv_bfloat16* sWh, __nv_bfloat16* sWl,
    __nv_bfloat16* sBDh, __nv_bfloat16* sBDl,
    int midx0, int t, const float* Bq, const float* Bk, const float* Bv,
    const __nv_bfloat16* BDhA, const __nv_bfloat16* BDlA,
    const __nv_bfloat16* BDhM, const __nv_bfloat16* BDlM,
    __half* OqH, __half* KVrh,
    const int* sList, int rem, int tid)
{
    int warp = tid >> 5, lane = tid & 31;
    int mbase = (warp & 3) * 32;
    int nbase = (warp >> 2) * 64;
    int rq = lane >> 2, cq = (lane & 3) * 2;

    #pragma unroll
    for (int s = 0; s < 3; s++) {
        if (s > 0) __syncthreads();
        load_w_smem(sWh, sWl, midx0 + s, t, tid);
        __syncthreads();

        float acc[2][8][4];
        #pragma unroll
        for (int i = 0; i < 2; i++)
            #pragma unroll
            for (int j = 0; j < 8; j++)
                #pragma unroll
                for (int q = 0; q < 4; q++) acc[i][j][q] = 0.f;

        mma_tile(acc, sAh, sAl, sWh, sWl, mbase, nbase, lane);

        const float* Bt = (s == 0 ? Bq : s == 1 ? Bk : Bv) + t * D_;

        if (s == 0) {
            #pragma unroll
            for (int mt = 0; mt < 2; mt++) {
                int rl0 = mbase + mt * 16 + rq;
                #pragma unroll
                for (int nt = 0; nt < 8; nt++) {
                    int col = nbase + nt * 8 + cq;
                    float b0 = Bt[col], b1 = Bt[col + 1];
                    float* a = acc[mt][nt];
                    #pragma unroll
                    for (int half = 0; half < 2; half++) {
                        int rl = rl0 + half * 8;
                        if (rl < rem)
                            *(__half2*)(OqH + (size_t)sList[rl] * D_ + col) =
                                __floats2half2_rn(a[half * 2] + b0, a[half * 2 + 1] + b1);
                    }
                }
            }
        } else {
            __syncthreads();   // all warps done reading sW
            #pragma unroll
            for (int mt = 0; mt < 2; mt++) {
                int rl0 = mbase + mt * 16 + rq;
                #pragma unroll
                for (int nt = 0; nt < 8; nt++) {
                    int col = nbase + nt * 8 + cq;
                    float b0 = Bt[col], b1 = Bt[col + 1];
                    float* a = acc[mt][nt];
                    #pragma unroll
                    for (int half = 0; half < 2; half++) {
                        int row = rl0 + half * 8;
                        float v0 = a[half * 2] + b0, v1 = a[half * 2 + 1] + b1;
                        __nv_bfloat16 h0 = __float2bfloat16_rn(v0);
                        __nv_bfloat16 h1 = __float2bfloat16_rn(v1);
                        __nv_bfloat16 l0 = __float2bfloat16_rn(v0 - __bfloat162float(h0));
                        __nv_bfloat16 l1 = __float2bfloat16_rn(v1 - __bfloat162float(h1));
                        *(unsigned*)(sWh + row * PAD_ + col) = pack_bf2(h0, h1);
                        *(unsigned*)(sWl + row * PAD_ + col) = pack_bf2(l0, l1);
                    }
                }
            }
            {
                const uint4* gh = (const uint4*)(s == 1 ? BDhA : BDhM);
                const uint4* gl = (const uint4*)(s == 1 ? BDlA : BDlM);
                uint4* dh = (uint4*)sBDh;
                uint4* dl = (uint4*)sBDl;
                #pragma unroll
                for (int it = 0; it < (R_ * BDSZ_ / 8 + 255) / 256; it++) {
                    int i = it * 256 + tid;
                    if (i < R_ * BDSZ_ / 8) { dh[i] = gh[i]; dl[i] = gl[i]; }
                }
            }
            __syncthreads();
            bd_transform_store(sWh, sWl, sBDh, sBDl, KVrh, (s == 1 ? 0 : 128),
                               sList, rem, mbase, nbase, lane);
        }
    }
}

// ---------------- QKV + relation-transform GEMM ----------------
__global__ void __launch_bounds__(256) k_qkvr_gemm(
    const float* __restrict__ in, int midx0,
    const float* __restrict__ Bq, const float* __restrict__ Bk, const float* __restrict__ Bv,
    const __nv_bfloat16* __restrict__ BDhA, const __nv_bfloat16* __restrict__ BDlA,
    const __nv_bfloat16* __restrict__ BDhM, const __nv_bfloat16* __restrict__ BDlM,
    __half* __restrict__ OqH, __half* __restrict__ KVrh)
{
    int t = blockIdx.y;
    int cnt = g_typeCnt[t];
    int base = blockIdx.x * 128;
    if (base >= cnt) return;
    const int* list = &g_typeList[t][base];
    int rem = cnt - base; if (rem > 128) rem = 128;

    extern __shared__ __nv_bfloat16 sm[];
    __nv_bfloat16* sAh = sm;
    __nv_bfloat16* sAl = sAh + 128 * PAD_;
    __nv_bfloat16* sWh = sAl + 128 * PAD_;
    __nv_bfloat16* sWl = sWh + 128 * PAD_;
    __nv_bfloat16* sBDh = sWl + 128 * PAD_;
    __nv_bfloat16* sBDl = sBDh + R_ * BDSZ_;
    __shared__ int sList[128];

    int tid = threadIdx.x;
    if (tid < 128) sList[tid] = (tid < rem) ? list[tid] : list[0];
    __syncthreads();

    load_a_smem(sAh, sAl, in, sList, 0, tid, nullptr);

    qkv_stages(sAh, sAl, sWh, sWl, sBDh, sBDl, midx0, t, Bq, Bk, Bv,
               BDhA, BDlA, BDhM, BDlM, OqH, KVrh, sList, rem, tid);
}

// ---------------- fused trans + next-layer QKV ----------------
__global__ void __launch_bounds__(256) k_trans_qkvr(
    const float* __restrict__ inA, int midxA,
    const float* __restrict__ BbaseA, float* __restrict__ outA,
    const float* __restrict__ prev, const float* __restrict__ skipv,
    const float* __restrict__ den,
    int midxQ,
    const float* __restrict__ Bq, const float* __restrict__ Bk, const float* __restrict__ Bv,
    const __nv_bfloat16* __restrict__ BDhA, const __nv_bfloat16* __restrict__ BDlA,
    const __nv_bfloat16* __restrict__ BDhM, const __nv_bfloat16* __restrict__ BDlM,
    __half* __restrict__ OqH, __half* __restrict__ KVrh)
{
    int t = blockIdx.y;
    int cnt = g_typeCnt[t];
    int base = blockIdx.x * 128;
    if (base >= cnt) return;
    const int* list = &g_typeList[t][base];
    int rem = cnt - base; if (rem > 128) rem = 128;

    extern __shared__ __nv_bfloat16 sm[];
    __nv_bfloat16* sAh = sm;
    __nv_bfloat16* sAl = sAh + 128 * PAD_;
    __nv_bfloat16* sWh = sAl + 128 * PAD_;
    __nv_bfloat16* sWl = sWh + 128 * PAD_;
    __nv_bfloat16* sBDh = sWl + 128 * PAD_;
    __nv_bfloat16* sBDl = sBDh + R_ * BDSZ_;
    __shared__ int sList[128];

    int tid = threadIdx.x;
    if (tid < 128) sList[tid] = (tid < rem) ? list[tid] : list[0];
    __syncthreads();

    load_a_smem(sAh, sAl, inA, sList, 2, tid, den);
    load_w_smem(sWh, sWl, midxA, t, tid);
    __syncthreads();

    int warp = tid >> 5, lane = tid & 31;
    int mbase = (warp & 3) * 32;
    int nbase = (warp >> 2) * 64;
    int rq = lane >> 2, cq = (lane & 3) * 2;

    float acc[2][8][4];
    #pragma unroll
    for (int i = 0; i < 2; i++)
        #pragma unroll
        for (int j = 0; j < 8; j++)
            #pragma unroll
            for (int q = 0; q < 4; q++) acc[i][j][q] = 0.f;

    mma_tile(acc, sAh, sAl, sWh, sWl, mbase, nbase, lane);
    __syncthreads();   // all warps done reading sAh/sAl

    {
        const float* Bt = BbaseA + t * D_;
        float alpha = 1.f / (1.f + expf(-skipv[t]));
        float beta = 1.f - alpha;
        #pragma unroll
        for (int mt = 0; mt < 2; mt++) {
            int rl0 = mbase + mt * 16 + rq;
            #pragma unroll
            for (int nt = 0; nt < 8; nt++) {
                int col = nbase + nt * 8 + cq;
                float b0 = Bt[col], b1 = Bt[col + 1];
                float* a = acc[mt][nt];
                #pragma unroll
                for (int half = 0; half < 2; half++) {
                    int row = rl0 + half * 8;
                    int grow = sList[row];
                    const float* pp = prev + (size_t)grow * D_ + col;
                    float2 old = *(const float2*)pp;
                    float v0 = alpha * (a[half * 2]     + b0) + beta * old.x;
                    float v1 = alpha * (a[half * 2 + 1] + b1) + beta * old.y;
                    if (row < rem)
                        *(float2*)(outA + (size_t)grow * D_ + col) = make_float2(v0, v1);
                    __nv_bfloat16 h0 = __float2bfloat16_rn(v0);
                    __nv_bfloat16 h1 = __float2bfloat16_rn(v1);
                    __nv_bfloat16 l0 = __float2bfloat16_rn(v0 - __bfloat162float(h0));
                    __nv_bfloat16 l1 = __float2bfloat16_rn(v1 - __bfloat162float(h1));
                    *(unsigned*)(sAh + row * PAD_ + col) = pack_bf2(h0, h1);
                    *(unsigned*)(sAl + row * PAD_ + col) = pack_bf2(l0, l1);
                }
            }
        }
    }
    qkv_stages(sAh, sAl, sWh, sWl, sBDh, sBDl, midxQ, t, Bq, Bk, Bv,
               BDhA, BDlA, BDhM, BDlM, OqH, KVrh, sList, rem, tid);
}

// ---------------- single typed GEMM (adapt / final trans) ----------------
__global__ void __launch_bounds__(256) k_typed_gemm(
    int inop, int outop,
    const float* __restrict__ in, int midx,
    const float* __restrict__ Bbase,
    float* __restrict__ out,
    const float* __restrict__ prev,
    const float* __restrict__ skipv,
    const float* __restrict__ den)
{
    int t = blockIdx.y;
    int cnt = g_typeCnt[t];
    int base = blockIdx.x * 128;
    if (base >= cnt) return;
    const int* list = &g_typeList[t][base];
    int rem = cnt - base; if (rem > 128) rem = 128;

    extern __shared__ __nv_bfloat16 sm[];
    __nv_bfloat16* sAh = sm;
    __nv_bfloat16* sAl = sAh + 128 * PAD_;
    __nv_bfloat16* sWh = sAl + 128 * PAD_;
    __nv_bfloat16* sWl = sWh + 128 * PAD_;
    __shared__ int sList[128];

    int tid = threadIdx.x;
    if (tid < 128) sList[tid] = (tid < rem) ? list[tid] : list[0];
    __syncthreads();

    load_a_smem(sAh, sAl, in, sList, inop, tid, den);
    load_w_smem(sWh, sWl, midx, t, tid);
    __syncthreads();

    int warp = tid >> 5, lane = tid & 31;
    int mbase = (warp & 3) * 32;
    int nbase = (warp >> 2) * 64;

    float acc[2][8][4];
    #pragma unroll
    for (int i = 0; i < 2; i++)
        #pragma unroll
        for (int j = 0; j < 8; j++)
            #pragma unroll
            for (int q = 0; q < 4; q++) acc[i][j][q] = 0.f;

    mma_tile(acc, sAh, sAl, sWh, sWl, mbase, nbase, lane);

    const float* Bt = Bbase + t * D_;
    float alpha = 0.f, beta = 0.f;
    if (outop == 2) { alpha = 1.f / (1.f + expf(-skipv[t])); beta = 1.f - alpha; }

    int rq = lane >> 2, cq = (lane & 3) * 2;
    #pragma unroll
    for (int mt = 0; mt < 2; mt++) {
        int rl0 = mbase + mt * 16 + rq;
        #pragma unroll
        for (int nt = 0; nt < 8; nt++) {
            int col = nbase + nt * 8 + cq;
            float b0 = Bt[col], b1 = Bt[col + 1];
            float* a = acc[mt][nt];
            #pragma unroll
            for (int half = 0; half < 2; half++) {
                int rl = rl0 + half * 8;
                if (rl < rem) {
                    int grow = sList[rl];
                    float v0 = a[half * 2]     + b0;
                    float v1 = a[half * 2 + 1] + b1;
                    if (outop == 1) { v0 = tanhf(v0); v1 = tanhf(v1); }
                    else if (outop == 2) {
                        const float* pp = prev + (size_t)grow * D_ + col;
                        float2 old = *(const float2*)pp;
                        v0 = alpha * v0 + beta * old.x;
                        v1 = alpha * v1 + beta * old.y;
                    }
                    *(float2*)(out + (size_t)grow * D_ + col) = make_float2(v0, v1);
                }
            }
        }
    }
}

// ---------------- fused edge pass (lean body, occupancy-forced) ----------------
__global__ void __launch_bounds__(256, 4) k_edgeAC(const __half* __restrict__ tabKV,
                                                   const float* __restrict__ relPri,
                                                   float* __restrict__ aggr,
                                                   float* __restrict__ den) {
    int r = blockIdx.y;
    int lo = g_bOff[r * NPB_], hi = g_bOff[(r + 1) * NPB_];
    int lane = threadIdx.x & 31;
    int h = lane & 7, esub = lane >> 3;
    int warp = blockIdx.x * (blockDim.x >> 5) + (threadIdx.x >> 5);
    int nwarp = gridDim.x * (blockDim.x >> 5);
    const __half* KVr = g_KVrh + (size_t)r * N_ * 256;
    const __half* tabR = tabKV + (size_t)r * T_ * ML_ * 256;

    for (int eb = lo + warp * 4; eb < hi; eb += nwarp * 4) {
        int p = eb + esub;
        bool valid = p < hi;
        int pp = valid ? p : lo;
        int s = g_eS[pp], t = g_eT[pp], meta = g_eMeta[pp];
        int st = meta & 3, tt = (meta >> 2) & 3, tm = meta >> 4;
        const __half* kvb = KVr + (size_t)s * 256 + h * 16;
        const __half* tbb = tabR + (size_t)(st * ML_ + tm) * 256 + h * 16;

        const uint4* kp = (const uint4*)kvb;
        const uint4* qp = (const uint4*)(g_Qh + (size_t)t * D_ + h * 16);
        const uint4* tp = (const uint4*)tbb;
        __half2 kh[8], qh[8], th[8];
        *(uint4*)(kh) = kp[0]; *(uint4*)(kh + 4) = kp[1];
        *(uint4*)(qh) = qp[0]; *(uint4*)(qh + 4) = qp[1];
        *(uint4*)(th) = tp[0]; *(uint4*)(th + 4) = tp[1];
        float sc = 0.f;
        #pragma unroll
        for (int i = 0; i < 8; i++) {
            float2 kf = __half22float2(kh[i]);
            float2 qf = __half22float2(qh[i]);
            float2 tf = __half22float2(th[i]);
            sc += qf.x * (kf.x + tf.x) + qf.y * (kf.y + tf.y);
        }
        float pri = relPri[((tt * R_ + r) * T_ + st) * H_ + h];
        // scores are O(1): exp without max-subtraction cannot overflow fp32;
        // softmax is shift-invariant so result is exact.
        float ex = expf(sc * pri * 0.25f);

        const uint4* vp = (const uint4*)(kvb + 128);
        const uint4* tvp = (const uint4*)(tbb + 128);
        __half2 vh[8], tvh[8];
        *(uint4*)(vh) = vp[0]; *(uint4*)(vh + 4) = vp[1];
        *(uint4*)(tvh) = tvp[0]; *(uint4*)(tvh + 4) = tvp[1];

        if (valid) {
            atomicAdd(&den[t * H_ + h], ex);
            float* op = aggr + (size_t)t * D_ + h * 16;
            #pragma unroll
            for (int i = 0; i < 4; i++) {
                float2 a = __half22float2(vh[2 * i]);
                float2 b = __half22float2(vh[2 * i + 1]);
                float2 ta = __half22float2(tvh[2 * i]);
                float2 tb = __half22float2(tvh[2 * i + 1]);
                red_add_v4(op + i * 4,
                           (a.x + ta.x) * ex, (a.y + ta.y) * ex,
                           (b.x + tb.x) * ex, (b.y + tb.y) * ex);
            }
        }
    }
}

// ---------------- launch ----------------
static cudaStream_t s1 = nullptr, s2 = nullptr, s3 = nullptr;
static cudaEvent_t evF = nullptr, evBuck = nullptr, evInit = nullptr;
static cudaEvent_t evTab0 = nullptr, evTab1 = nullptr, evW0 = nullptr, evW1 = nullptr;

extern "C" void kernel_launch(void* const* d_in, const int* in_sizes, int n_in,
                              void* d_out, int out_size) {
    const float* node_feature = (const float*)d_in[0];
    const int*   node_type    = (const int*)d_in[1];
    const int*   edge_index   = (const int*)d_in[2];
    const int*   edge_type    = (const int*)d_in[3];
    const int*   edge_time    = (const int*)d_in[4];
    const float* adapt_w      = (const float*)d_in[5];
    const float* adapt_b      = (const float*)d_in[6];
    const float* Wk           = (const float*)d_in[7];
    const float* bk           = (const float*)d_in[8];
    const float* Wq           = (const float*)d_in[9];
    const float* bq           = (const float*)d_in[10];
    const float* Wv           = (const float*)d_in[11];
    const float* bv           = (const float*)d_in[12];
    const float* Wa           = (const float*)d_in[13];
    const float* ba           = (const float*)d_in[14];
    const float* rel_pri      = (const float*)d_in[15];
    const float* rel_att      = (const float*)d_in[16];
    const float* rel_msg      = (const float*)d_in[17];
    const float* skip         = (const float*)d_in[18];
    const float* rte_w        = (const float*)d_in[19];
    const float* rte_b        = (const float*)d_in[20];

    const int* src = edge_index;
    const int* tgt = edge_index + E_;

    if (!s1) {
        cudaStreamCreateWithFlags(&s1, cudaStreamNonBlocking);
        cudaStreamCreateWithFlags(&s2, cudaStreamNonBlocking);
        cudaStreamCreateWithFlags(&s3, cudaStreamNonBlocking);
        cudaEventCreateWithFlags(&evF, cudaEventDisableTiming);
        cudaEventCreateWithFlags(&evBuck, cudaEventDisableTiming);
        cudaEventCreateWithFlags(&evInit, cudaEventDisableTiming);
        cudaEventCreateWithFlags(&evTab0, cudaEventDisableTiming);
        cudaEventCreateWithFlags(&evTab1, cudaEventDisableTiming);
        cudaEventCreateWithFlags(&evW0, cudaEventDisableTiming);
        cudaEventCreateWithFlags(&evW1, cudaEventDisableTiming);
        cudaFuncSetAttribute(k_typed_gemm, cudaFuncAttributeMaxDynamicSharedMemorySize, GEMM_SMEM);
        cudaFuncSetAttribute(k_qkvr_gemm, cudaFuncAttributeMaxDynamicSharedMemorySize, QKVR_SMEM);
        cudaFuncSetAttribute(k_trans_qkvr, cudaFuncAttributeMaxDynamicSharedMemorySize, QKVR_SMEM);
    }

    float *px, *pa0, *pa1, *pd0, *pd1;
    __half *pQh, *pKVrh, *ptKV0;
    __nv_bfloat16 *pBDh, *pBDl;
    cudaGetSymbolAddress((void**)&px, g_x);
    cudaGetSymbolAddress((void**)&pQh, g_Qh);
    cudaGetSymbolAddress((void**)&pa0, g_aggr);
    pa1 = pa0 + TD_;
    cudaGetSymbolAddress((void**)&pd0, g_den);
    pd1 = pd0 + N_ * H_;
    cudaGetSymbolAddress((void**)&pKVrh, g_KVrh);
    cudaGetSymbolAddress((void**)&ptKV0, g_tabKVh);
    cudaGetSymbolAddress((void**)&pBDh, g_BDh);
    cudaGetSymbolAddress((void**)&pBDl, g_BDl);
    const size_t TABSTRIDE = (size_t)R_ * T_ * ML_ * 256;

    dim3 ggrid((N_ + 127) / 128, T_);
    dim3 egrid(256, R_);
    const int WSPLIT_GRID = (T_ * D_ * D_ + 255) / 256;
    size_t woff1 = (size_t)T_ * 128 * 128;

    // fork all three side streams from the capture origin
    cudaEventRecord(evF, 0);
    cudaStreamWaitEvent(s1, evF, 0);
    cudaStreamWaitEvent(s2, evF, 0);
    cudaStreamWaitEvent(s3, evF, 0);

    // s1: edge bucketing + layer-buffer zeroing
    k_init_bkt<<<(NB_ + 255) / 256, 256, 0, s1>>>();
    k_count_b<<<(E_ + 255) / 256, 256, 0, s1>>>(tgt, edge_type);
    k_scan_b<<<1, 1024, 0, s1>>>();
    k_scatter_b<<<(E_ + 255) / 256, 256, 0, s1>>>(src, tgt, edge_type, edge_time, node_type);
    cudaEventRecord(evBuck, s1);
    k_init_layer<<<2048, 256, 0, s1>>>();   // zero both layers' aggr/den
    cudaEventRecord(evInit, s1);

    // s2: RTE tables (layer 0 then layer 1)
    k_rte_tab<<<ML_, 128, 0, s2>>>();
    k_rte_proj<<<ML_, 128, 0, s2>>>(rte_w, rte_b);
    k_tables<<<T_ * ML_, 128, 0, s2>>>(Wk, Wv, rel_att, rel_msg, 0);
    cudaEventRecord(evTab0, s2);
    k_rte_proj<<<ML_, 128, 0, s2>>>(rte_w + (size_t)256 * 128, rte_b + 128);
    k_tables<<<T_ * ML_, 128, 0, s2>>>(Wk + woff1, Wv + woff1,
                                       rel_att + (size_t)R_ * H_ * 256,
                                       rel_msg + (size_t)R_ * H_ * 256, 1);
    cudaEventRecord(evTab1, s2);

    // s3: weight splits (layer-0 QKV first, then the rest)
    k_relsplit<<<(2 * 2 * R_ * H_ * 256 + 255) / 256, 256, 0, s3>>>(rel_att, rel_msg);
    k_wsplit<<<WSPLIT_GRID, 256, 0, s3>>>(Wq, 1);
    k_wsplit<<<WSPLIT_GRID, 256, 0, s3>>>(Wk, 2);
    k_wsplit<<<WSPLIT_GRID, 256, 0, s3>>>(Wv, 3);
    cudaEventRecord(evW0, s3);
    k_wsplit<<<WSPLIT_GRID, 256, 0, s3>>>(Wa, 4);
    k_wsplit<<<WSPLIT_GRID, 256, 0, s3>>>(Wq + woff1, 5);
    k_wsplit<<<WSPLIT_GRID, 256, 0, s3>>>(Wk + woff1, 6);
    k_wsplit<<<WSPLIT_GRID, 256, 0, s3>>>(Wv + woff1, 7);
    k_wsplit<<<WSPLIT_GRID, 256, 0, s3>>>(Wa + woff1, 8);
    cudaEventRecord(evW1, s3);

    // main: type buckets + adapt GEMM
    k_init_type<<<1, 32>>>();
    k_build_type<<<(N_ + 255) / 256, 256>>>(node_type);
    k_wsplit<<<WSPLIT_GRID, 256>>>(adapt_w, 0);
    k_typed_gemm<<<ggrid, 256, GEMM_SMEM>>>(0, 1, node_feature, 0, adapt_b, px, px, nullptr, nullptr);

    cudaStreamWaitEvent(0, evW0, 0);   // Wq/Wk/Wv(l0) + BD splits ready
    k_qkvr_gemm<<<ggrid, 256, QKVR_SMEM>>>(
        px, 1, bq, bk, bv,
        pBDh + 0 * R_ * BDSZ_, pBDl + 0 * R_ * BDSZ_,
        pBDh + 1 * R_ * BDSZ_, pBDl + 1 * R_ * BDSZ_,
        pQh, pKVrh);

    cudaStreamWaitEvent(0, evBuck, 0);
    cudaStreamWaitEvent(0, evTab0, 0);
    cudaStreamWaitEvent(0, evInit, 0);
    k_edgeAC<<<egrid, 256>>>(ptKV0, rel_pri, pa0, pd0);

    cudaStreamWaitEvent(0, evW1, 0);   // Wa(l0) + l1 weights ready
    k_trans_qkvr<<<ggrid, 256, QKVR_SMEM>>>(
        pa0, 4, ba, px, px, skip, pd0,
        5, bq + T_ * 128, bk + T_ * 128, bv + T_ * 128,
        pBDh + 2 * R_ * BDSZ_, pBDl + 2 * R_ * BDSZ_,
        pBDh + 3 * R_ * BDSZ_, pBDl + 3 * R_ * BDSZ_,
        pQh, pKVrh);

    cudaStreamWaitEvent(0, evTab1, 0);
    k_edgeAC<<<egrid, 256>>>(ptKV0 + TABSTRIDE, rel_pri + (size_t)T_ * R_ * T_ * H_, pa1, pd1);

    // final trans -> d_out
    k_typed_gemm<<<ggrid, 256, GEMM_SMEM>>>(2, 2, pa1, 8, ba + T_ * 128,
                                            (float*)d_out, px, skip + T_, pd1);
}

// round 16
// speedup vs baseline: 1.0745x; 1.0673x over previous
#include <cuda_runtime.h>
#include <cuda_bf16.h>
#include <cuda_fp16.h>
#include <math.h>

#define N_ 100000
#define E_ 500000
#define D_ 128
#define T_ 3
#define R_ 4
#define H_ 8
#define ML_ 240
#define TD_ ((size_t)N_*(size_t)D_)
#define PAD_ 136
#define BDPAD_ 24
#define BDSZ_ (H_*16*BDPAD_)
#define GEMM_SMEM ((2 * 128 * PAD_ + 2 * 64 * PAD_) * 2)   // A hi/lo + W-half hi/lo = 102KB
#define QKVR_SMEM ((4 * 128 * PAD_ + 2 * R_ * BDSZ_) * 2)
#define NMAT_ 9
#define NPB_ ((N_ + 127) / 128)
#define NB_  (R_ * NPB_)

__device__ float g_x[TD_];
__device__ __half g_Qh[TD_];
__device__ float g_aggr[2][TD_];          // per-layer unnormalized U
__device__ float g_den[2][N_*H_];
__device__ __half g_KVrh[(size_t)R_*N_*2*D_];   // K at +0, V at +128 (per node)
__device__ float g_rte_tab[ML_*2*D_];
__device__ float g_rte_proj[ML_*D_];
__device__ __half g_tabKVh[2][(size_t)R_*T_*ML_*2*D_];  // K at +0, V at +128
__device__ __nv_bfloat16 g_Wh[(size_t)NMAT_*T_*D_*D_];
__device__ __nv_bfloat16 g_Wl[(size_t)NMAT_*T_*D_*D_];
__device__ __nv_bfloat16 g_BDh[2*2*R_*BDSZ_];
__device__ __nv_bfloat16 g_BDl[2*2*R_*BDSZ_];
__device__ int   g_typeList[T_][N_];
__device__ int   g_typeCnt[T_];
__device__ int   g_bCnt[NB_];
__device__ int   g_bOff[NB_+1];
__device__ int   g_bFill[NB_];
__device__ int   g_eS[E_];
__device__ int   g_eT[E_];
__device__ int   g_eMeta[E_];   // st | tt<<2 | time<<4

__device__ __forceinline__ float gelu_f(float x) { return x * normcdff(x); }

__device__ __forceinline__ void red_add_v4(float* p, float a, float b, float c, float d) {
    asm volatile("red.global.add.v4.f32 [%0], {%1,%2,%3,%4};"
                 :: "l"(p), "f"(a), "f"(b), "f"(c), "f"(d) : "memory");
}

// ---------------- mma helpers ----------------
__device__ __forceinline__ void ldsm4(unsigned& r0, unsigned& r1, unsigned& r2, unsigned& r3,
                                      unsigned addr) {
    asm volatile("ldmatrix.sync.aligned.m8n8.x4.shared.b16 {%0,%1,%2,%3}, [%4];"
                 : "=r"(r0), "=r"(r1), "=r"(r2), "=r"(r3) : "r"(addr));
}
__device__ __forceinline__ void ldsm4t(unsigned& r0, unsigned& r1, unsigned& r2, unsigned& r3,
                                       unsigned addr) {
    asm volatile("ldmatrix.sync.aligned.m8n8.x4.trans.shared.b16 {%0,%1,%2,%3}, [%4];"
                 : "=r"(r0), "=r"(r1), "=r"(r2), "=r"(r3) : "r"(addr));
}
__device__ __forceinline__ void mma16816(float* d, const unsigned* a, const unsigned* b) {
    asm volatile("mma.sync.aligned.m16n8k16.row.col.f32.bf16.bf16.f32 "
                 "{%0,%1,%2,%3}, {%4,%5,%6,%7}, {%8,%9}, {%0,%1,%2,%3};"
                 : "+f"(d[0]), "+f"(d[1]), "+f"(d[2]), "+f"(d[3])
                 : "r"(a[0]), "r"(a[1]), "r"(a[2]), "r"(a[3]), "r"(b[0]), "r"(b[1]));
}
__device__ __forceinline__ unsigned pack_bf2(__nv_bfloat16 a, __nv_bfloat16 b) {
    __nv_bfloat162 p(a, b);
    return *reinterpret_cast<unsigned*>(&p);
}

// ---------------- precompute kernels ----------------
__global__ void k_rte_tab() {
    int pos = blockIdx.x;
    int i   = threadIdx.x;
    const float s = 0.08838834764831845f;
    float div;
    if (i >= 5) div = 0.f;   // fp32 10000^ar overflow -> inf -> 0
    else {
        float pf = (float)pow(10000.0, (double)(2 * i));
        div = 1.0f / ((pf / 128.0f) / 2.0f);
    }
    float ang = (float)pos * div;
    double a = (double)ang;
    g_rte_tab[pos * 256 + 2 * i]     = (float)sin(a) * s;
    g_rte_tab[pos * 256 + 2 * i + 1] = (float)cos(a) * s;
}

__global__ void k_rte_proj(const float* __restrict__ w, const float* __restrict__ b) {
    int time = blockIdx.x;
    int d    = threadIdx.x;
    float acc = b[d];
    const float* tr = g_rte_tab + time * 256;
    for (int c = 0; c < 256; c++) acc += tr[c] * w[c * 128 + d];
    g_rte_proj[time * 128 + d] = acc;
}

__global__ void k_tables(const float* __restrict__ Wk, const float* __restrict__ Wv,
                         const float* __restrict__ relAtt, const float* __restrict__ relMsg,
                         int l) {
    __shared__ float sK[128], sV[128];
    int id = blockIdx.x;
    int d  = threadIdx.x;
    int t = id / ML_, time = id % ML_;
    const float* pr = g_rte_proj + time * 128;
    const float* wk = Wk + (size_t)t * 128 * 128;
    const float* wv = Wv + (size_t)t * 128 * 128;
    float aK = 0.f, aV = 0.f;
    for (int k = 0; k < 128; k++) {
        float p = pr[k];
        aK += p * wk[k * 128 + d];
        aV += p * wv[k * 128 + d];
    }
    sK[d] = aK; sV[d] = aV;
    __syncthreads();
    int h = d >> 4, dk = d & 15;
    size_t rowoff = (size_t)(t * ML_ + time) * 256 + d;
    for (int r = 0; r < R_; r++) {
        const float* A = relAtt + ((size_t)r * H_ + h) * 256;
        const float* M = relMsg + ((size_t)r * H_ + h) * 256;
        float k2 = 0.f, v2 = 0.f;
        #pragma unroll
        for (int j = 0; j < 16; j++) {
            k2 += sK[h * 16 + j] * A[j * 16 + dk];
            v2 += sV[h * 16 + j] * M[j * 16 + dk];
        }
        g_tabKVh[l][(size_t)r * T_ * ML_ * 256 + rowoff]       = __float2half_rn(k2);
        g_tabKVh[l][(size_t)r * T_ * ML_ * 256 + rowoff + 128] = __float2half_rn(v2);
    }
}

__global__ void k_wsplit(const float* __restrict__ src, int midx) {
    int i = blockIdx.x * blockDim.x + threadIdx.x;
    int n = T_ * D_ * D_;
    if (i >= n) return;
    size_t off = (size_t)midx * n + i;
    float v = src[i];
    __nv_bfloat16 h = __float2bfloat16_rn(v);
    g_Wh[off] = h;
    g_Wl[off] = __float2bfloat16_rn(v - __bfloat162float(h));
}

__global__ void k_relsplit(const float* __restrict__ relAtt, const float* __restrict__ relMsg) {
    int idx = blockIdx.x * blockDim.x + threadIdx.x;
    if (idx >= 2 * 2 * R_ * H_ * 256) return;
    int c = idx & 15, k = (idx >> 4) & 15, h = (idx >> 8) & 7;
    int r = (idx >> 11) & 3, w = (idx >> 13) & 1, l = idx >> 14;
    const float* src = w ? relMsg : relAtt;
    float v = src[(((size_t)l * R_ + r) * H_ + h) * 256 + k * 16 + c];
    __nv_bfloat16 hi = __float2bfloat16_rn(v);
    size_t dst = (size_t)(((l * 2 + w) * R_ + r)) * BDSZ_ + (h * 16 + k) * BDPAD_ + c;
    g_BDh[dst] = hi;
    g_BDl[dst] = __float2bfloat16_rn(v - __bfloat162float(hi));
}

// ---------------- bucketing ----------------
__global__ void k_init_bkt() {
    int i = blockIdx.x * blockDim.x + threadIdx.x;
    if (i < NB_) { g_bCnt[i] = 0; g_bFill[i] = 0; }
}

__global__ void k_init_type() {
    if (threadIdx.x < T_) g_typeCnt[threadIdx.x] = 0;
}

__global__ void k_build_type(const int* __restrict__ nt) {
    __shared__ int c[T_];
    __shared__ int base[T_];
    int tid = threadIdx.x;
    if (tid < T_) c[tid] = 0;
    __syncthreads();
    int i = blockIdx.x * blockDim.x + tid;
    int t = -1, rank = 0;
    if (i < N_) { t = nt[i]; rank = atomicAdd(&c[t], 1); }
    __syncthreads();
    if (tid < T_) base[tid] = c[tid] ? atomicAdd(&g_typeCnt[tid], c[tid]) : 0;
    __syncthreads();
    if (i < N_) g_typeList[t][base[t] + rank] = i;
}

__global__ void k_count_b(const int* __restrict__ tgt, const int* __restrict__ et) {
    int i = blockIdx.x * blockDim.x + threadIdx.x;
    if (i < E_) atomicAdd(&g_bCnt[et[i] * NPB_ + (tgt[i] >> 7)], 1);
}

__global__ void __launch_bounds__(1024) k_scan_b() {
    __shared__ int wsum[32];
    int tid = threadIdx.x;
    int v[4], s = 0;
    #pragma unroll
    for (int i = 0; i < 4; i++) {
        int idx = tid * 4 + i;
        v[i] = (idx < NB_) ? g_bCnt[idx] : 0;
        s += v[i];
    }
    int lane = tid & 31, w = tid >> 5;
    int incl = s;
    #pragma unroll
    for (int d = 1; d < 32; d <<= 1) {
        int o = __shfl_up_sync(0xffffffffu, incl, d);
        if (lane >= d) incl += o;
    }
    if (lane == 31) wsum[w] = incl;
    __syncthreads();
    if (w == 0) {
        int x = (lane < 32) ? wsum[lane] : 0;
        int in2 = x;
        #pragma unroll
        for (int d = 1; d < 32; d <<= 1) {
            int o = __shfl_up_sync(0xffffffffu, in2, d);
            if (lane >= d) in2 += o;
        }
        wsum[lane] = in2 - x;
    }
    __syncthreads();
    int excl = wsum[w] + incl - s;
    #pragma unroll
    for (int i = 0; i < 4; i++) {
        int idx = tid * 4 + i;
        if (idx < NB_) g_bOff[idx] = excl;
        excl += v[i];
    }
    if (tid == 1023) g_bOff[NB_] = E_;
}

__global__ void k_scatter_b(const int* __restrict__ src, const int* __restrict__ tgt,
                            const int* __restrict__ et, const int* __restrict__ etm,
                            const int* __restrict__ nt) {
    int e = blockIdx.x * blockDim.x + threadIdx.x;
    if (e < E_) {
        int t = tgt[e];
        int key = et[e] * NPB_ + (t >> 7);
        int p = g_bOff[key] + atomicAdd(&g_bFill[key], 1);
        int s = src[e];
        g_eS[p] = s;
        g_eT[p] = t;
        g_eMeta[p] = nt[s] | (nt[t] << 2) | (etm[e] << 4);
    }
}

__global__ void k_init_layer() {
    size_t stride = (size_t)gridDim.x * blockDim.x;
    size_t i0 = (size_t)blockIdx.x * blockDim.x + threadIdx.x;
    for (size_t i = i0; i < 2 * (size_t)N_ * H_; i += stride) g_den[0][i] = 0.f;
    for (size_t i = i0; i < 2 * TD_; i += stride) g_aggr[0][i] = 0.f;
}

// ---------------- GEMM building blocks ----------------
__device__ __forceinline__ void load_w_smem(__nv_bfloat16* sWh, __nv_bfloat16* sWl,
                                            int midx, int t, int tid) {
    size_t base = ((size_t)midx * T_ + t) * D_ * D_;
    const uint4* wh4 = (const uint4*)(g_Wh + base);
    const uint4* wl4 = (const uint4*)(g_Wl + base);
    #pragma unroll
    for (int it = 0; it < 8; it++) {
        int idx = it * 256 + tid;
        int row = idx >> 4;
        int col = (idx & 15) * 8;
        *(uint4*)(sWh + row * PAD_ + col) = wh4[idx];
        *(uint4*)(sWl + row * PAD_ + col) = wl4[idx];
    }
}

// load 64 K-rows of W (half kh) into a 64-row smem buffer
__device__ __forceinline__ void load_w_smem_half(__nv_bfloat16* sWh, __nv_bfloat16* sWl,
                                                 int midx, int t, int kh, int tid) {
    size_t base = ((size_t)midx * T_ + t) * D_ * D_ + (size_t)kh * 64 * D_;
    const uint4* wh4 = (const uint4*)(g_Wh + base);
    const uint4* wl4 = (const uint4*)(g_Wl + base);
    #pragma unroll
    for (int it = 0; it < 4; it++) {
        int idx = it * 256 + tid;          // uint4 over 64x128 bf16 (1024)
        int row = idx >> 4;
        int col = (idx & 15) * 8;
        *(uint4*)(sWh + row * PAD_ + col) = wh4[idx];
        *(uint4*)(sWl + row * PAD_ + col) = wl4[idx];
    }
}

__device__ __forceinline__ void cvt_store(__nv_bfloat16* sAh, __nv_bfloat16* sAl,
                                          int row, int col, float4 v) {
    __nv_bfloat16 h0 = __float2bfloat16_rn(v.x), h1 = __float2bfloat16_rn(v.y);
    __nv_bfloat16 h2 = __float2bfloat16_rn(v.z), h3 = __float2bfloat16_rn(v.w);
    __nv_bfloat16 l0 = __float2bfloat16_rn(v.x - __bfloat162float(h0));
    __nv_bfloat16 l1 = __float2bfloat16_rn(v.y - __bfloat162float(h1));
    __nv_bfloat16 l2 = __float2bfloat16_rn(v.z - __bfloat162float(h2));
    __nv_bfloat16 l3 = __float2bfloat16_rn(v.w - __bfloat162float(h3));
    *(uint2*)(sAh + row * PAD_ + col) = make_uint2(pack_bf2(h0, h1), pack_bf2(h2, h3));
    *(uint2*)(sAl + row * PAD_ + col) = make_uint2(pack_bf2(l0, l1), pack_bf2(l2, l3));
}

// inop: 0=none, 1=gelu(v), 2=gelu(v/den)
__device__ __forceinline__ void load_a_smem(__nv_bfloat16* sAh, __nv_bfloat16* sAl,
                                            const float* __restrict__ in,
                                            const int* sList, int inop, int tid,
                                            const float* __restrict__ den) {
    #pragma unroll
    for (int it = 0; it < 16; it++) {
        int idx = it * 256 + tid;
        int row = idx >> 5;
        int col = (idx & 31) << 2;
        int grow = sList[row];
        float4 v = *(const float4*)(in + (size_t)grow * D_ + col);
        if (inop == 1) {
            v.x = gelu_f(v.x); v.y = gelu_f(v.y); v.z = gelu_f(v.z); v.w = gelu_f(v.w);
        } else if (inop == 2) {
            float dv = den[grow * H_ + (col >> 4)];
            float inv = dv > 0.f ? 1.f / dv : 0.f;
            v.x = gelu_f(v.x * inv); v.y = gelu_f(v.y * inv);
            v.z = gelu_f(v.z * inv); v.w = gelu_f(v.w * inv);
        }
        cvt_store(sAh, sAl, row, col, v);
    }
}

__device__ __forceinline__ void mma_tile(float (&acc)[2][8][4],
                                         const __nv_bfloat16* sAh, const __nv_bfloat16* sAl,
                                         const __nv_bfloat16* sWh, const __nv_bfloat16* sWl,
                                         int mbase, int nbase, int lane) {
    int aRow = mbase + (lane & 15);
    int aColAdd = (lane >> 4) << 3;
    int bg = lane >> 3;
    int bRowAdd = ((bg & 1) << 3) + (lane & 7);
    int bColAdd = (bg >> 1) << 3;

    unsigned aHbase = (unsigned)__cvta_generic_to_shared(sAh + aRow * PAD_);
    unsigned aLbase = (unsigned)__cvta_generic_to_shared(sAl + aRow * PAD_);
    unsigned wHbase = (unsigned)__cvta_generic_to_shared(sWh);
    unsigned wLbase = (unsigned)__cvta_generic_to_shared(sWl);

    #pragma unroll
    for (int kc = 0; kc < 8; kc++) {
        int k0 = kc * 16;
        unsigned ah[2][4], al[2][4];
        #pragma unroll
        for (int mt = 0; mt < 2; mt++) {
            unsigned off = (mt * 16 * PAD_ + k0 + aColAdd) * 2;
            ldsm4(ah[mt][0], ah[mt][1], ah[mt][2], ah[mt][3], aHbase + off);
            ldsm4(al[mt][0], al[mt][1], al[mt][2], al[mt][3], aLbase + off);
        }
        #pragma unroll
        for (int nt2 = 0; nt2 < 4; nt2++) {
            int nb = nbase + nt2 * 16;
            unsigned off = ((k0 + bRowAdd) * PAD_ + nb + bColAdd) * 2;
            unsigned bh[4], bl[4];
            ldsm4t(bh[0], bh[1], bh[2], bh[3], wHbase + off);
            ldsm4t(bl[0], bl[1], bl[2], bl[3], wLbase + off);
            #pragma unroll
            for (int mt = 0; mt < 2; mt++) {
                mma16816(acc[mt][nt2 * 2],     ah[mt], bh);
                mma16816(acc[mt][nt2 * 2],     al[mt], bh);
                mma16816(acc[mt][nt2 * 2],     ah[mt], bl);
                mma16816(acc[mt][nt2 * 2 + 1], ah[mt], bh + 2);
                mma16816(acc[mt][nt2 * 2 + 1], al[mt], bh + 2);
                mma16816(acc[mt][nt2 * 2 + 1], ah[mt], bl + 2);
            }
        }
    }
}

// K-split variant: A is full 128-K; W buffer holds 64 K-rows (half kh).
__device__ __forceinline__ void mma_tile_ks(float (&acc)[2][8][4],
                                            const __nv_bfloat16* sAh, const __nv_bfloat16* sAl,
                                            const __nv_bfloat16* sWh, const __nv_bfloat16* sWl,
                                            int mbase, int nbase, int lane, int kh) {
    int aRow = mbase + (lane & 15);
    int aColAdd = (lane >> 4) << 3;
    int bg = lane >> 3;
    int bRowAdd = ((bg & 1) << 3) + (lane & 7);
    int bColAdd = (bg >> 1) << 3;

    unsigned aHbase = (unsigned)__cvta_generic_to_shared(sAh + aRow * PAD_);
    unsigned aLbase = (unsigned)__cvta_generic_to_shared(sAl + aRow * PAD_);
    unsigned wHbase = (unsigned)__cvta_generic_to_shared(sWh);
    unsigned wLbase = (unsigned)__cvta_generic_to_shared(sWl);

    #pragma unroll
    for (int kc = 0; kc < 4; kc++) {
        int k0A = kh * 64 + kc * 16;   // A: absolute K offset
        int k0W = kc * 16;             // W: local row in half buffer
        unsigned ah[2][4], al[2][4];
        #pragma unroll
        for (int mt = 0; mt < 2; mt++) {
            unsigned off = (mt * 16 * PAD_ + k0A + aColAdd) * 2;
            ldsm4(ah[mt][0], ah[mt][1], ah[mt][2], ah[mt][3], aHbase + off);
            ldsm4(al[mt][0], al[mt][1], al[mt][2], al[mt][3], aLbase + off);
        }
        #pragma unroll
        for (int nt2 = 0; nt2 < 4; nt2++) {
            int nb = nbase + nt2 * 16;
            unsigned off = ((k0W + bRowAdd) * PAD_ + nb + bColAdd) * 2;
            unsigned bh[4], bl[4];
            ldsm4t(bh[0], bh[1], bh[2], bh[3], wHbase + off);
            ldsm4t(bl[0], bl[1], bl[2], bl[3], wLbase + off);
            #pragma unroll
            for (int mt = 0; mt < 2; mt++) {
                mma16816(acc[mt][nt2 * 2],     ah[mt], bh);
                mma16816(acc[mt][nt2 * 2],     al[mt], bh);
                mma16816(acc[mt][nt2 * 2],     ah[mt], bl);
                mma16816(acc[mt][nt2 * 2 + 1], ah[mt], bh + 2);
                mma16816(acc[mt][nt2 * 2 + 1], al[mt], bh + 2);
                mma16816(acc[mt][nt2 * 2 + 1], ah[mt], bl + 2);
            }
        }
    }
}

// block-diag relation transform of tile in sTh/sTl; scatter fp16 to
// KVout[r][node][koff + 0..127] (interleaved K/V layout, node stride 256).
__device__ __forceinline__ void bd_transform_store(
    const __nv_bfloat16* sTh, const __nv_bfloat16* sTl,
    const __nv_bfloat16* sBDh, const __nv_bfloat16* sBDl,
    __half* __restrict__ KVout, int koff, const int* sList, int rem,
    int mbase, int nbase, int lane)
{
    int aColAdd = (lane >> 4) << 3;
    int bg = lane >> 3;
    int bRowAdd = ((bg & 1) << 3) + (lane & 7);
    int bColAdd = (bg >> 1) << 3;
    unsigned aHbase = (unsigned)__cvta_generic_to_shared(sTh + (mbase + (lane & 15)) * PAD_);
    unsigned aLbase = (unsigned)__cvta_generic_to_shared(sTl + (mbase + (lane & 15)) * PAD_);
    int rq = lane >> 2, cq = (lane & 3) * 2;

    #pragma unroll
    for (int r = 0; r < R_; r++) {
        unsigned bHbase = (unsigned)__cvta_generic_to_shared(sBDh + r * BDSZ_);
        unsigned bLbase = (unsigned)__cvta_generic_to_shared(sBDl + r * BDSZ_);
        __half* outR = KVout + (size_t)r * N_ * 256 + koff;
        #pragma unroll
        for (int nt2 = 0; nt2 < 4; nt2++) {
            int head = (nbase >> 4) + nt2;
            unsigned ah[2][4], al[2][4];
            #pragma unroll
            for (int mt = 0; mt < 2; mt++) {
                unsigned offA = (mt * 16 * PAD_ + head * 16 + aColAdd) * 2;
                ldsm4(ah[mt][0], ah[mt][1], ah[mt][2], ah[mt][3], aHbase + offA);
                ldsm4(al[mt][0], al[mt][1], al[mt][2], al[mt][3], aLbase + offA);
            }
            unsigned offB = ((head * 16 + bRowAdd) * BDPAD_ + bColAdd) * 2;
            unsigned bh[4], bl[4];
            ldsm4t(bh[0], bh[1], bh[2], bh[3], bHbase + offB);
            ldsm4t(bl[0], bl[1], bl[2], bl[3], bLbase + offB);

            float acc[2][2][4];
            #pragma unroll
            for (int mt = 0; mt < 2; mt++)
                #pragma unroll
                for (int n8 = 0; n8 < 2; n8++)
                    #pragma unroll
                    for (int q = 0; q < 4; q++) acc[mt][n8][q] = 0.f;
            #pragma unroll
            for (int mt = 0; mt < 2; mt++) {
                mma16816(acc[mt][0], ah[mt], bh);
                mma16816(acc[mt][0], al[mt], bh);
                mma16816(acc[mt][0], ah[mt], bl);
                mma16816(acc[mt][1], ah[mt], bh + 2);
                mma16816(acc[mt][1], al[mt], bh + 2);
                mma16816(acc[mt][1], ah[mt], bl + 2);
            }
            #pragma unroll
            for (int mt = 0; mt < 2; mt++) {
                int rl0 = mbase + mt * 16 + rq;
                #pragma unroll
                for (int n8 = 0; n8 < 2; n8++) {
                    int col = head * 16 + n8 * 8 + cq;
                    float* a = acc[mt][n8];
                    #pragma unroll
                    for (int half = 0; half < 2; half++) {
                        int rl = rl0 + half * 8;
                        if (rl < rem)
                            *(__half2*)(outR + (size_t)sList[rl] * 256 + col) =
                                __floats2half2_rn(a[half * 2], a[half * 2 + 1]);
                    }
                }
            }
        }
    }
}

// QKV stages over the A tile resident in sAh/sAl.
__device__ __forceinline__ void qkv_stages(
    __nv_bfloat16* sAh, __nv_bfloat16* sAl, __nv_bfloat16* sWh, __nv_bfloat16* sWl,
    __nv_bfloat16* sBDh, __nv_bfloat16* sBDl,
    int midx0, int t, const float* Bq, const float* Bk, const float* Bv,
    const __nv_bfloat16* BDhA, const __nv_bfloat16* BDlA,
    const __nv_bfloat16* BDhM, const __nv_bfloat16* BDlM,
    __half* OqH, __half* KVrh,
    const int* sList, int rem, int tid)
{
    int warp = tid >> 5, lane = tid & 31;
    int mbase = (warp & 3) * 32;
    int nbase = (warp >> 2) * 64;
    int rq = lane >> 2, cq = (lane & 3) * 2;

    #pragma unroll
    for (int s = 0; s < 3; s++) {
        if (s > 0) __syncthreads();
        load_w_smem(sWh, sWl, midx0 + s, t, tid);
        __syncthreads();

        float acc[2][8][4];
        #pragma unroll
        for (int i = 0; i < 2; i++)
            #pragma unroll
            for (int j = 0; j < 8; j++)
                #pragma unroll
                for (int q = 0; q < 4; q++) acc[i][j][q] = 0.f;

        mma_tile(acc, sAh, sAl, sWh, sWl, mbase, nbase, lane);

        const float* Bt = (s == 0 ? Bq : s == 1 ? Bk : Bv) + t * D_;

        if (s == 0) {
            #pragma unroll
            for (int mt = 0; mt < 2; mt++) {
                int rl0 = mbase + mt * 16 + rq;
                #pragma unroll
                for (int nt = 0; nt < 8; nt++) {
                    int col = nbase + nt * 8 + cq;
                    float b0 = Bt[col], b1 = Bt[col + 1];
                    float* a = acc[mt][nt];
                    #pragma unroll
                    for (int half = 0; half < 2; half++) {
                        int rl = rl0 + half * 8;
                        if (rl < rem)
                            *(__half2*)(OqH + (size_t)sList[rl] * D_ + col) =
                                __floats2half2_rn(a[half * 2] + b0, a[half * 2 + 1] + b1);
                    }
                }
            }
        } else {
            __syncthreads();   // all warps done reading sW
            #pragma unroll
            for (int mt = 0; mt < 2; mt++) {
                int rl0 = mbase + mt * 16 + rq;
                #pragma unroll
                for (int nt = 0; nt < 8; nt++) {
                    int col = nbase + nt * 8 + cq;
                    float b0 = Bt[col], b1 = Bt[col + 1];
                    float* a = acc[mt][nt];
                    #pragma unroll
                    for (int half = 0; half < 2; half++) {
                        int row = rl0 + half * 8;
                        float v0 = a[half * 2] + b0, v1 = a[half * 2 + 1] + b1;
                        __nv_bfloat16 h0 = __float2bfloat16_rn(v0);
                        __nv_bfloat16 h1 = __float2bfloat16_rn(v1);
                        __nv_bfloat16 l0 = __float2bfloat16_rn(v0 - __bfloat162float(h0));
                        __nv_bfloat16 l1 = __float2bfloat16_rn(v1 - __bfloat162float(h1));
                        *(unsigned*)(sWh + row * PAD_ + col) = pack_bf2(h0, h1);
                        *(unsigned*)(sWl + row * PAD_ + col) = pack_bf2(l0, l1);
                    }
                }
            }
            {
                const uint4* gh = (const uint4*)(s == 1 ? BDhA : BDhM);
                const uint4* gl = (const uint4*)(s == 1 ? BDlA : BDlM);
                uint4* dh = (uint4*)sBDh;
                uint4* dl = (uint4*)sBDl;
                #pragma unroll
                for (int it = 0; it < (R_ * BDSZ_ / 8 + 255) / 256; it++) {
                    int i = it * 256 + tid;
                    if (i < R_ * BDSZ_ / 8) { dh[i] = gh[i]; dl[i] = gl[i]; }
                }
            }
            __syncthreads();
            bd_transform_store(sWh, sWl, sBDh, sBDl, KVrh, (s == 1 ? 0 : 128),
                               sList, rem, mbase, nbase, lane);
        }
    }
}

// ---------------- QKV + relation-transform GEMM ----------------
__global__ void __launch_bounds__(256) k_qkvr_gemm(
    const float* __restrict__ in, int midx0,
    const float* __restrict__ Bq, const float* __restrict__ Bk, const float* __restrict__ Bv,
    const __nv_bfloat16* __restrict__ BDhA, const __nv_bfloat16* __restrict__ BDlA,
    const __nv_bfloat16* __restrict__ BDhM, const __nv_bfloat16* __restrict__ BDlM,
    __half* __restrict__ OqH, __half* __restrict__ KVrh)
{
    int t = blockIdx.y;
    int cnt = g_typeCnt[t];
    int base = blockIdx.x * 128;
    if (base >= cnt) return;
    const int* list = &g_typeList[t][base];
    int rem = cnt - base; if (rem > 128) rem = 128;

    extern __shared__ __nv_bfloat16 sm[];
    __nv_bfloat16* sAh = sm;
    __nv_bfloat16* sAl = sAh + 128 * PAD_;
    __nv_bfloat16* sWh = sAl + 128 * PAD_;
    __nv_bfloat16* sWl = sWh + 128 * PAD_;
    __nv_bfloat16* sBDh = sWl + 128 * PAD_;
    __nv_bfloat16* sBDl = sBDh + R_ * BDSZ_;
    __shared__ int sList[128];

    int tid = threadIdx.x;
    if (tid < 128) sList[tid] = (tid < rem) ? list[tid] : list[0];
    __syncthreads();

    load_a_smem(sAh, sAl, in, sList, 0, tid, nullptr);

    qkv_stages(sAh, sAl, sWh, sWl, sBDh, sBDl, midx0, t, Bq, Bk, Bv,
               BDhA, BDlA, BDhM, BDlM, OqH, KVrh, sList, rem, tid);
}

// ---------------- fused trans + next-layer QKV ----------------
__global__ void __launch_bounds__(256) k_trans_qkvr(
    const float* __restrict__ inA, int midxA,
    const float* __restrict__ BbaseA, float* __restrict__ outA,
    const float* __restrict__ prev, const float* __restrict__ skipv,
    const float* __restrict__ den,
    int midxQ,
    const float* __restrict__ Bq, const float* __restrict__ Bk, const float* __restrict__ Bv,
    const __nv_bfloat16* __restrict__ BDhA, const __nv_bfloat16* __restrict__ BDlA,
    const __nv_bfloat16* __restrict__ BDhM, const __nv_bfloat16* __restrict__ BDlM,
    __half* __restrict__ OqH, __half* __restrict__ KVrh)
{
    int t = blockIdx.y;
    int cnt = g_typeCnt[t];
    int base = blockIdx.x * 128;
    if (base >= cnt) return;
    const int* list = &g_typeList[t][base];
    int rem = cnt - base; if (rem > 128) rem = 128;

    extern __shared__ __nv_bfloat16 sm[];
    __nv_bfloat16* sAh = sm;
    __nv_bfloat16* sAl = sAh + 128 * PAD_;
    __nv_bfloat16* sWh = sAl + 128 * PAD_;
    __nv_bfloat16* sWl = sWh + 128 * PAD_;
    __nv_bfloat16* sBDh = sWl + 128 * PAD_;
    __nv_bfloat16* sBDl = sBDh + R_ * BDSZ_;
    __shared__ int sList[128];

    int tid = threadIdx.x;
    if (tid < 128) sList[tid] = (tid < rem) ? list[tid] : list[0];
    __syncthreads();

    load_a_smem(sAh, sAl, inA, sList, 2, tid, den);
    load_w_smem(sWh, sWl, midxA, t, tid);
    __syncthreads();

    int warp = tid >> 5, lane = tid & 31;
    int mbase = (warp & 3) * 32;
    int nbase = (warp >> 2) * 64;
    int rq = lane >> 2, cq = (lane & 3) * 2;

    float acc[2][8][4];
    #pragma unroll
    for (int i = 0; i < 2; i++)
        #pragma unroll
        for (int j = 0; j < 8; j++)
            #pragma unroll
            for (int q = 0; q < 4; q++) acc[i][j][q] = 0.f;

    mma_tile(acc, sAh, sAl, sWh, sWl, mbase, nbase, lane);
    __syncthreads();   // all warps done reading sAh/sAl

    {
        const float* Bt = BbaseA + t * D_;
        float alpha = 1.f / (1.f + expf(-skipv[t]));
        float beta = 1.f - alpha;
        #pragma unroll
        for (int mt = 0; mt < 2; mt++) {
            int rl0 = mbase + mt * 16 + rq;
            #pragma unroll
            for (int nt = 0; nt < 8; nt++) {
                int col = nbase + nt * 8 + cq;
                float b0 = Bt[col], b1 = Bt[col + 1];
                float* a = acc[mt][nt];
                #pragma unroll
                for (int half = 0; half < 2; half++) {
                    int row = rl0 + half * 8;
                    int grow = sList[row];
                    const float* pp = prev + (size_t)grow * D_ + col;
                    float2 old = *(const float2*)pp;
                    float v0 = alpha * (a[half * 2]     + b0) + beta * old.x;
                    float v1 = alpha * (a[half * 2 + 1] + b1) + beta * old.y;
                    if (row < rem)
                        *(float2*)(outA + (size_t)grow * D_ + col) = make_float2(v0, v1);
                    __nv_bfloat16 h0 = __float2bfloat16_rn(v0);
                    __nv_bfloat16 h1 = __float2bfloat16_rn(v1);
                    __nv_bfloat16 l0 = __float2bfloat16_rn(v0 - __bfloat162float(h0));
                    __nv_bfloat16 l1 = __float2bfloat16_rn(v1 - __bfloat162float(h1));
                    *(unsigned*)(sAh + row * PAD_ + col) = pack_bf2(h0, h1);
                    *(unsigned*)(sAl + row * PAD_ + col) = pack_bf2(l0, l1);
                }
            }
        }
    }
    qkv_stages(sAh, sAl, sWh, sWl, sBDh, sBDl, midxQ, t, Bq, Bk, Bv,
               BDhA, BDlA, BDhM, BDlM, OqH, KVrh, sList, rem, tid);
}

// ---------------- single typed GEMM (adapt / final trans), K-split W, 2 CTA/SM ----------------
__global__ void __launch_bounds__(256, 2) k_typed_gemm(
    int inop, int outop,
    const float* __restrict__ in, int midx,
    const float* __restrict__ Bbase,
    float* __restrict__ out,
    const float* __restrict__ prev,
    const float* __restrict__ skipv,
    const float* __restrict__ den)
{
    int t = blockIdx.y;
    int cnt = g_typeCnt[t];
    int base = blockIdx.x * 128;
    if (base >= cnt) return;
    const int* list = &g_typeList[t][base];
    int rem = cnt - base; if (rem > 128) rem = 128;

    extern __shared__ __nv_bfloat16 sm[];
    __nv_bfloat16* sAh = sm;
    __nv_bfloat16* sAl = sAh + 128 * PAD_;
    __nv_bfloat16* sWh = sAl + 128 * PAD_;      // 64-row half buffer
    __nv_bfloat16* sWl = sWh + 64 * PAD_;
    __shared__ int sList[128];

    int tid = threadIdx.x;
    if (tid < 128) sList[tid] = (tid < rem) ? list[tid] : list[0];
    __syncthreads();

    load_a_smem(sAh, sAl, in, sList, inop, tid, den);
    load_w_smem_half(sWh, sWl, midx, t, 0, tid);
    __syncthreads();

    int warp = tid >> 5, lane = tid & 31;
    int mbase = (warp & 3) * 32;
    int nbase = (warp >> 2) * 64;

    float acc[2][8][4];
    #pragma unroll
    for (int i = 0; i < 2; i++)
        #pragma unroll
        for (int j = 0; j < 8; j++)
            #pragma unroll
            for (int q = 0; q < 4; q++) acc[i][j][q] = 0.f;

    mma_tile_ks(acc, sAh, sAl, sWh, sWl, mbase, nbase, lane, 0);
    __syncthreads();                              // mma reads of sW done
    load_w_smem_half(sWh, sWl, midx, t, 1, tid);
    __syncthreads();
    mma_tile_ks(acc, sAh, sAl, sWh, sWl, mbase, nbase, lane, 1);

    const float* Bt = Bbase + t * D_;
    float alpha = 0.f, beta = 0.f;
    if (outop == 2) { alpha = 1.f / (1.f + expf(-skipv[t])); beta = 1.f - alpha; }

    int rq = lane >> 2, cq = (lane & 3) * 2;
    #pragma unroll
    for (int mt = 0; mt < 2; mt++) {
        int rl0 = mbase + mt * 16 + rq;
        #pragma unroll
        for (int nt = 0; nt < 8; nt++) {
            int col = nbase + nt * 8 + cq;
            float b0 = Bt[col], b1 = Bt[col + 1];
            float* a = acc[mt][nt];
            #pragma unroll
            for (int half = 0; half < 2; half++) {
                int rl = rl0 + half * 8;
                if (rl < rem) {
                    int grow = sList[rl];
                    float v0 = a[half * 2]     + b0;
                    float v1 = a[half * 2 + 1] + b1;
                    if (outop == 1) { v0 = tanhf(v0); v1 = tanhf(v1); }
                    else if (outop == 2) {
                        const float* pp = prev + (size_t)grow * D_ + col;
                        float2 old = *(const float2*)pp;
                        v0 = alpha * v0 + beta * old.x;
                        v1 = alpha * v1 + beta * old.y;
                    }
                    *(float2*)(out + (size_t)grow * D_ + col) = make_float2(v0, v1);
                }
            }
        }
    }
}

// ---------------- fused edge pass (lean body, occupancy-forced) ----------------
__global__ void __launch_bounds__(256, 4) k_edgeAC(const __half* __restrict__ tabKV,
                                                   const float* __restrict__ relPri,
                                                   float* __restrict__ aggr,
                                                   float* __restrict__ den) {
    int r = blockIdx.y;
    int lo = g_bOff[r * NPB_], hi = g_bOff[(r + 1) * NPB_];
    int lane = threadIdx.x & 31;
    int h = lane & 7, esub = lane >> 3;
    int warp = blockIdx.x * (blockDim.x >> 5) + (threadIdx.x >> 5);
    int nwarp = gridDim.x * (blockDim.x >> 5);
    const __half* KVr = g_KVrh + (size_t)r * N_ * 256;
    const __half* tabR = tabKV + (size_t)r * T_ * ML_ * 256;

    for (int eb = lo + warp * 4; eb < hi; eb += nwarp * 4) {
        int p = eb + esub;
        bool valid = p < hi;
        int pp = valid ? p : lo;
        int s = g_eS[pp], t = g_eT[pp], meta = g_eMeta[pp];
        int st = meta & 3, tt = (meta >> 2) & 3, tm = meta >> 4;
        const __half* kvb = KVr + (size_t)s * 256 + h * 16;
        const __half* tbb = tabR + (size_t)(st * ML_ + tm) * 256 + h * 16;

        const uint4* kp = (const uint4*)kvb;
        const uint4* qp = (const uint4*)(g_Qh + (size_t)t * D_ + h * 16);
        const uint4* tp = (const uint4*)tbb;
        __half2 kh[8], qh[8], th[8];
        *(uint4*)(kh) = kp[0]; *(uint4*)(kh + 4) = kp[1];
        *(uint4*)(qh) = qp[0]; *(uint4*)(qh + 4) = qp[1];
        *(uint4*)(th) = tp[0]; *(uint4*)(th + 4) = tp[1];
        float sc = 0.f;
        #pragma unroll
        for (int i = 0; i < 8; i++) {
            float2 kf = __half22float2(kh[i]);
            float2 qf = __half22float2(qh[i]);
            float2 tf = __half22float2(th[i]);
            sc += qf.x * (kf.x + tf.x) + qf.y * (kf.y + tf.y);
        }
        float pri = relPri[((tt * R_ + r) * T_ + st) * H_ + h];
        // scores are O(1): exp without max-subtraction cannot overflow fp32;
        // softmax is shift-invariant so result is exact.
        float ex = expf(sc * pri * 0.25f);

        const uint4* vp = (const uint4*)(kvb + 128);
        const uint4* tvp = (const uint4*)(tbb + 128);
        __half2 vh[8], tvh[8];
        *(uint4*)(vh) = vp[0]; *(uint4*)(vh + 4) = vp[1];
        *(uint4*)(tvh) = tvp[0]; *(uint4*)(tvh + 4) = tvp[1];

        if (valid) {
            atomicAdd(&den[t * H_ + h], ex);
            float* op = aggr + (size_t)t * D_ + h * 16;
            #pragma unroll
            for (int i = 0; i < 4; i++) {
                float2 a = __half22float2(vh[2 * i]);
                float2 b = __half22float2(vh[2 * i + 1]);
                float2 ta = __half22float2(tvh[2 * i]);
                float2 tb = __half22float2(tvh[2 * i + 1]);
                red_add_v4(op + i * 4,
                           (a.x + ta.x) * ex, (a.y + ta.y) * ex,
                           (b.x + tb.x) * ex, (b.y + tb.y) * ex);
            }
        }
    }
}

// ---------------- launch ----------------
static cudaStream_t s1 = nullptr, s2 = nullptr, s3 = nullptr;
static cudaEvent_t evF = nullptr, evBuck = nullptr, evInit = nullptr;
static cudaEvent_t evTab0 = nullptr, evTab1 = nullptr, evW0 = nullptr, evW1 = nullptr;

extern "C" void kernel_launch(void* const* d_in, const int* in_sizes, int n_in,
                              void* d_out, int out_size) {
    const float* node_feature = (const float*)d_in[0];
    const int*   node_type    = (const int*)d_in[1];
    const int*   edge_index   = (const int*)d_in[2];
    const int*   edge_type    = (const int*)d_in[3];
    const int*   edge_time    = (const int*)d_in[4];
    const float* adapt_w      = (const float*)d_in[5];
    const float* adapt_b      = (const float*)d_in[6];
    const float* Wk           = (const float*)d_in[7];
    const float* bk           = (const float*)d_in[8];
    const float* Wq           = (const float*)d_in[9];
    const float* bq           = (const float*)d_in[10];
    const float* Wv           = (const float*)d_in[11];
    const float* bv           = (const float*)d_in[12];
    const float* Wa           = (const float*)d_in[13];
    const float* ba           = (const float*)d_in[14];
    const float* rel_pri      = (const float*)d_in[15];
    const float* rel_att      = (const float*)d_in[16];
    const float* rel_msg      = (const float*)d_in[17];
    const float* skip         = (const float*)d_in[18];
    const float* rte_w        = (const float*)d_in[19];
    const float* rte_b        = (const float*)d_in[20];

    const int* src = edge_index;
    const int* tgt = edge_index + E_;

    if (!s1) {
        cudaStreamCreateWithFlags(&s1, cudaStreamNonBlocking);
        cudaStreamCreateWithFlags(&s2, cudaStreamNonBlocking);
        cudaStreamCreateWithFlags(&s3, cudaStreamNonBlocking);
        cudaEventCreateWithFlags(&evF, cudaEventDisableTiming);
        cudaEventCreateWithFlags(&evBuck, cudaEventDisableTiming);
        cudaEventCreateWithFlags(&evInit, cudaEventDisableTiming);
        cudaEventCreateWithFlags(&evTab0, cudaEventDisableTiming);
        cudaEventCreateWithFlags(&evTab1, cudaEventDisableTiming);
        cudaEventCreateWithFlags(&evW0, cudaEventDisableTiming);
        cudaEventCreateWithFlags(&evW1, cudaEventDisableTiming);
        cudaFuncSetAttribute(k_typed_gemm, cudaFuncAttributeMaxDynamicSharedMemorySize, GEMM_SMEM);
        cudaFuncSetAttribute(k_qkvr_gemm, cudaFuncAttributeMaxDynamicSharedMemorySize, QKVR_SMEM);
        cudaFuncSetAttribute(k_trans_qkvr, cudaFuncAttributeMaxDynamicSharedMemorySize, QKVR_SMEM);
    }

    float *px, *pa0, *pa1, *pd0, *pd1;
    __half *pQh, *pKVrh, *ptKV0;
    __nv_bfloat16 *pBDh, *pBDl;
    cudaGetSymbolAddress((void**)&px, g_x);
    cudaGetSymbolAddress((void**)&pQh, g_Qh);
    cudaGetSymbolAddress((void**)&pa0, g_aggr);
    pa1 = pa0 + TD_;
    cudaGetSymbolAddress((void**)&pd0, g_den);
    pd1 = pd0 + N_ * H_;
    cudaGetSymbolAddress((void**)&pKVrh, g_KVrh);
    cudaGetSymbolAddress((void**)&ptKV0, g_tabKVh);
    cudaGetSymbolAddress((void**)&pBDh, g_BDh);
    cudaGetSymbolAddress((void**)&pBDl, g_BDl);
    const size_t TABSTRIDE = (size_t)R_ * T_ * ML_ * 256;

    dim3 ggrid((N_ + 127) / 128, T_);
    dim3 egrid(256, R_);
    const int WSPLIT_GRID = (T_ * D_ * D_ + 255) / 256;
    size_t woff1 = (size_t)T_ * 128 * 128;

    // fork all three side streams from the capture origin
    cudaEventRecord(evF, 0);
    cudaStreamWaitEvent(s1, evF, 0);
    cudaStreamWaitEvent(s2, evF, 0);
    cudaStreamWaitEvent(s3, evF, 0);

    // s1: edge bucketing + layer-buffer zeroing
    k_init_bkt<<<(NB_ + 255) / 256, 256, 0, s1>>>();
    k_count_b<<<(E_ + 255) / 256, 256, 0, s1>>>(tgt, edge_type);
    k_scan_b<<<1, 1024, 0, s1>>>();
    k_scatter_b<<<(E_ + 255) / 256, 256, 0, s1>>>(src, tgt, edge_type, edge_time, node_type);
    cudaEventRecord(evBuck, s1);
    k_init_layer<<<2048, 256, 0, s1>>>();   // zero both layers' aggr/den
    cudaEventRecord(evInit, s1);

    // s2: RTE tables (layer 0 then layer 1)
    k_rte_tab<<<ML_, 128, 0, s2>>>();
    k_rte_proj<<<ML_, 128, 0, s2>>>(rte_w, rte_b);
    k_tables<<<T_ * ML_, 128, 0, s2>>>(Wk, Wv, rel_att, rel_msg, 0);
    cudaEventRecord(evTab0, s2);
    k_rte_proj<<<ML_, 128, 0, s2>>>(rte_w + (size_t)256 * 128, rte_b + 128);
    k_tables<<<T_ * ML_, 128, 0, s2>>>(Wk + woff1, Wv + woff1,
                                       rel_att + (size_t)R_ * H_ * 256,
                                       rel_msg + (size_t)R_ * H_ * 256, 1);
    cudaEventRecord(evTab1, s2);

    // s3: weight splits (layer-0 QKV first, then the rest)
    k_relsplit<<<(2 * 2 * R_ * H_ * 256 + 255) / 256, 256, 0, s3>>>(rel_att, rel_msg);
    k_wsplit<<<WSPLIT_GRID, 256, 0, s3>>>(Wq, 1);
    k_wsplit<<<WSPLIT_GRID, 256, 0, s3>>>(Wk, 2);
    k_wsplit<<<WSPLIT_GRID, 256, 0, s3>>>(Wv, 3);
    cudaEventRecord(evW0, s3);
    k_wsplit<<<WSPLIT_GRID, 256, 0, s3>>>(Wa, 4);
    k_wsplit<<<WSPLIT_GRID, 256, 0, s3>>>(Wq + woff1, 5);
    k_wsplit<<<WSPLIT_GRID, 256, 0, s3>>>(Wk + woff1, 6);
    k_wsplit<<<WSPLIT_GRID, 256, 0, s3>>>(Wv + woff1, 7);
    k_wsplit<<<WSPLIT_GRID, 256, 0, s3>>>(Wa + woff1, 8);
    cudaEventRecord(evW1, s3);

    // main: type buckets + adapt GEMM
    k_init_type<<<1, 32>>>();
    k_build_type<<<(N_ + 255) / 256, 256>>>(node_type);
    k_wsplit<<<WSPLIT_GRID, 256>>>(adapt_w, 0);
    k_typed_gemm<<<ggrid, 256, GEMM_SMEM>>>(0, 1, node_feature, 0, adapt_b, px, px, nullptr, nullptr);

    cudaStreamWaitEvent(0, evW0, 0);   // Wq/Wk/Wv(l0) + BD splits ready
    k_qkvr_gemm<<<ggrid, 256, QKVR_SMEM>>>(
        px, 1, bq, bk, bv,
        pBDh + 0 * R_ * BDSZ_, pBDl + 0 * R_ * BDSZ_,
        pBDh + 1 * R_ * BDSZ_, pBDl + 1 * R_ * BDSZ_,
        pQh, pKVrh);

    cudaStreamWaitEvent(0, evBuck, 0);
    cudaStreamWaitEvent(0, evTab0, 0);
    cudaStreamWaitEvent(0, evInit, 0);
    k_edgeAC<<<egrid, 256>>>(ptKV0, rel_pri, pa0, pd0);

    cudaStreamWaitEvent(0, evW1, 0);   // Wa(l0) + l1 weights ready
    k_trans_qkvr<<<ggrid, 256, QKVR_SMEM>>>(
        pa0, 4, ba, px, px, skip, pd0,
        5, bq + T_ * 128, bk + T_ * 128, bv + T_ * 128,
        pBDh + 2 * R_ * BDSZ_, pBDl + 2 * R_ * BDSZ_,
        pBDh + 3 * R_ * BDSZ_, pBDl + 3 * R_ * BDSZ_,
        pQh, pKVrh);

    cudaStreamWaitEvent(0, evTab1, 0);
    k_edgeAC<<<egrid, 256>>>(ptKV0 + TABSTRIDE, rel_pri + (size_t)T_ * R_ * T_ * H_, pa1, pd1);

    // final trans -> d_out
    k_typed_gemm<<<ggrid, 256, GEMM_SMEM>>>(2, 2, pa1, 8, ba + T_ * 128,
                                            (float*)d_out, px, skip + T_, pd1);
}

// round 17
// speedup vs baseline: 1.1707x; 1.0896x over previous
#include <cuda_runtime.h>
#include <cuda_bf16.h>
#include <cuda_fp16.h>
#include <math.h>

#define N_ 100000
#define E_ 500000
#define D_ 128
#define T_ 3
#define R_ 4
#define H_ 8
#define ML_ 240
#define TD_ ((size_t)N_*(size_t)D_)
#define PAD_ 136
#define BDPAD_ 24
#define BDSZ_ (H_*16*BDPAD_)
#define GEMM_SMEM ((2 * 128 * PAD_ + 2 * 64 * PAD_) * 2)   // 102KB: 2 CTA/SM
#define QKVR_SMEM ((4 * 128 * PAD_ + 2 * R_ * BDSZ_) * 2)  // 184KB: 1 CTA/SM, 512 thr
#define NMAT_ 9
#define NPB_ ((N_ + 127) / 128)
#define NB_  (R_ * NPB_)

__device__ float g_x[TD_];
__device__ __half g_Qh[TD_];
__device__ float g_aggr[2][TD_];
__device__ float g_den[2][N_*H_];
__device__ __half g_KVrh[(size_t)R_*N_*2*D_];   // K at +0, V at +128 (per node)
__device__ float g_rte_tab[ML_*2*D_];
__device__ float g_rte_proj[ML_*D_];
__device__ __half g_tabKVh[2][(size_t)R_*T_*ML_*2*D_];
__device__ __nv_bfloat16 g_Wh[(size_t)NMAT_*T_*D_*D_];
__device__ __nv_bfloat16 g_Wl[(size_t)NMAT_*T_*D_*D_];
__device__ __nv_bfloat16 g_BDh[2*2*R_*BDSZ_];
__device__ __nv_bfloat16 g_BDl[2*2*R_*BDSZ_];
__device__ int   g_typeList[T_][N_];
__device__ int   g_typeCnt[T_];
__device__ int   g_bCnt[NB_];
__device__ int   g_bOff[NB_+1];
__device__ int   g_bFill[NB_];
__device__ int   g_eS[E_];
__device__ int   g_eT[E_];
__device__ int   g_eMeta[E_];   // st | tt<<2 | time<<4

__device__ __forceinline__ float gelu_f(float x) { return x * normcdff(x); }

__device__ __forceinline__ void red_add_v4(float* p, float a, float b, float c, float d) {
    asm volatile("red.global.add.v4.f32 [%0], {%1,%2,%3,%4};"
                 :: "l"(p), "f"(a), "f"(b), "f"(c), "f"(d) : "memory");
}

// ---------------- mma helpers ----------------
__device__ __forceinline__ void ldsm4(unsigned& r0, unsigned& r1, unsigned& r2, unsigned& r3,
                                      unsigned addr) {
    asm volatile("ldmatrix.sync.aligned.m8n8.x4.shared.b16 {%0,%1,%2,%3}, [%4];"
                 : "=r"(r0), "=r"(r1), "=r"(r2), "=r"(r3) : "r"(addr));
}
__device__ __forceinline__ void ldsm4t(unsigned& r0, unsigned& r1, unsigned& r2, unsigned& r3,
                                       unsigned addr) {
    asm volatile("ldmatrix.sync.aligned.m8n8.x4.trans.shared.b16 {%0,%1,%2,%3}, [%4];"
                 : "=r"(r0), "=r"(r1), "=r"(r2), "=r"(r3) : "r"(addr));
}
__device__ __forceinline__ void mma16816(float* d, const unsigned* a, const unsigned* b) {
    asm volatile("mma.sync.aligned.m16n8k16.row.col.f32.bf16.bf16.f32 "
                 "{%0,%1,%2,%3}, {%4,%5,%6,%7}, {%8,%9}, {%0,%1,%2,%3};"
                 : "+f"(d[0]), "+f"(d[1]), "+f"(d[2]), "+f"(d[3])
                 : "r"(a[0]), "r"(a[1]), "r"(a[2]), "r"(a[3]), "r"(b[0]), "r"(b[1]));
}
__device__ __forceinline__ unsigned pack_bf2(__nv_bfloat16 a, __nv_bfloat16 b) {
    __nv_bfloat162 p(a, b);
    return *reinterpret_cast<unsigned*>(&p);
}

// ---------------- precompute kernels ----------------
__global__ void k_rte_tab() {
    int pos = blockIdx.x;
    int i   = threadIdx.x;
    const float s = 0.08838834764831845f;
    float div;
    if (i >= 5) div = 0.f;   // fp32 10000^ar overflow -> inf -> 0
    else {
        float pf = (float)pow(10000.0, (double)(2 * i));
        div = 1.0f / ((pf / 128.0f) / 2.0f);
    }
    float ang = (float)pos * div;
    double a = (double)ang;
    g_rte_tab[pos * 256 + 2 * i]     = (float)sin(a) * s;
    g_rte_tab[pos * 256 + 2 * i + 1] = (float)cos(a) * s;
}

__global__ void k_rte_proj(const float* __restrict__ w, const float* __restrict__ b) {
    int time = blockIdx.x;
    int d    = threadIdx.x;
    float acc = b[d];
    const float* tr = g_rte_tab + time * 256;
    for (int c = 0; c < 256; c++) acc += tr[c] * w[c * 128 + d];
    g_rte_proj[time * 128 + d] = acc;
}

__global__ void k_tables(const float* __restrict__ Wk, const float* __restrict__ Wv,
                         const float* __restrict__ relAtt, const float* __restrict__ relMsg,
                         int l) {
    __shared__ float sK[128], sV[128];
    int id = blockIdx.x;
    int d  = threadIdx.x;
    int t = id / ML_, time = id % ML_;
    const float* pr = g_rte_proj + time * 128;
    const float* wk = Wk + (size_t)t * 128 * 128;
    const float* wv = Wv + (size_t)t * 128 * 128;
    float aK = 0.f, aV = 0.f;
    for (int k = 0; k < 128; k++) {
        float p = pr[k];
        aK += p * wk[k * 128 + d];
        aV += p * wv[k * 128 + d];
    }
    sK[d] = aK; sV[d] = aV;
    __syncthreads();
    int h = d >> 4, dk = d & 15;
    size_t rowoff = (size_t)(t * ML_ + time) * 256 + d;
    for (int r = 0; r < R_; r++) {
        const float* A = relAtt + ((size_t)r * H_ + h) * 256;
        const float* M = relMsg + ((size_t)r * H_ + h) * 256;
        float k2 = 0.f, v2 = 0.f;
        #pragma unroll
        for (int j = 0; j < 16; j++) {
            k2 += sK[h * 16 + j] * A[j * 16 + dk];
            v2 += sV[h * 16 + j] * M[j * 16 + dk];
        }
        g_tabKVh[l][(size_t)r * T_ * ML_ * 256 + rowoff]       = __float2half_rn(k2);
        g_tabKVh[l][(size_t)r * T_ * ML_ * 256 + rowoff + 128] = __float2half_rn(v2);
    }
}

__global__ void k_wsplit(const float* __restrict__ src, int midx) {
    int i = blockIdx.x * blockDim.x + threadIdx.x;
    int n = T_ * D_ * D_;
    if (i >= n) return;
    size_t off = (size_t)midx * n + i;
    float v = src[i];
    __nv_bfloat16 h = __float2bfloat16_rn(v);
    g_Wh[off] = h;
    g_Wl[off] = __float2bfloat16_rn(v - __bfloat162float(h));
}

__global__ void k_relsplit(const float* __restrict__ relAtt, const float* __restrict__ relMsg) {
    int idx = blockIdx.x * blockDim.x + threadIdx.x;
    if (idx >= 2 * 2 * R_ * H_ * 256) return;
    int c = idx & 15, k = (idx >> 4) & 15, h = (idx >> 8) & 7;
    int r = (idx >> 11) & 3, w = (idx >> 13) & 1, l = idx >> 14;
    const float* src = w ? relMsg : relAtt;
    float v = src[(((size_t)l * R_ + r) * H_ + h) * 256 + k * 16 + c];
    __nv_bfloat16 hi = __float2bfloat16_rn(v);
    size_t dst = (size_t)(((l * 2 + w) * R_ + r)) * BDSZ_ + (h * 16 + k) * BDPAD_ + c;
    g_BDh[dst] = hi;
    g_BDl[dst] = __float2bfloat16_rn(v - __bfloat162float(hi));
}

// ---------------- bucketing ----------------
__global__ void k_init_bkt() {
    int i = blockIdx.x * blockDim.x + threadIdx.x;
    if (i < NB_) { g_bCnt[i] = 0; g_bFill[i] = 0; }
}

__global__ void k_init_type() {
    if (threadIdx.x < T_) g_typeCnt[threadIdx.x] = 0;
}

__global__ void k_build_type(const int* __restrict__ nt) {
    __shared__ int c[T_];
    __shared__ int base[T_];
    int tid = threadIdx.x;
    if (tid < T_) c[tid] = 0;
    __syncthreads();
    int i = blockIdx.x * blockDim.x + tid;
    int t = -1, rank = 0;
    if (i < N_) { t = nt[i]; rank = atomicAdd(&c[t], 1); }
    __syncthreads();
    if (tid < T_) base[tid] = c[tid] ? atomicAdd(&g_typeCnt[tid], c[tid]) : 0;
    __syncthreads();
    if (i < N_) g_typeList[t][base[t] + rank] = i;
}

__global__ void k_count_b(const int* __restrict__ tgt, const int* __restrict__ et) {
    int i = blockIdx.x * blockDim.x + threadIdx.x;
    if (i < E_) atomicAdd(&g_bCnt[et[i] * NPB_ + (tgt[i] >> 7)], 1);
}

__global__ void __launch_bounds__(1024) k_scan_b() {
    __shared__ int wsum[32];
    int tid = threadIdx.x;
    int v[4], s = 0;
    #pragma unroll
    for (int i = 0; i < 4; i++) {
        int idx = tid * 4 + i;
        v[i] = (idx < NB_) ? g_bCnt[idx] : 0;
        s += v[i];
    }
    int lane = tid & 31, w = tid >> 5;
    int incl = s;
    #pragma unroll
    for (int d = 1; d < 32; d <<= 1) {
        int o = __shfl_up_sync(0xffffffffu, incl, d);
        if (lane >= d) incl += o;
    }
    if (lane == 31) wsum[w] = incl;
    __syncthreads();
    if (w == 0) {
        int x = (lane < 32) ? wsum[lane] : 0;
        int in2 = x;
        #pragma unroll
        for (int d = 1; d < 32; d <<= 1) {
            int o = __shfl_up_sync(0xffffffffu, in2, d);
            if (lane >= d) in2 += o;
        }
        wsum[lane] = in2 - x;
    }
    __syncthreads();
    int excl = wsum[w] + incl - s;
    #pragma unroll
    for (int i = 0; i < 4; i++) {
        int idx = tid * 4 + i;
        if (idx < NB_) g_bOff[idx] = excl;
        excl += v[i];
    }
    if (tid == 1023) g_bOff[NB_] = E_;
}

__global__ void k_scatter_b(const int* __restrict__ src, const int* __restrict__ tgt,
                            const int* __restrict__ et, const int* __restrict__ etm,
                            const int* __restrict__ nt) {
    int e = blockIdx.x * blockDim.x + threadIdx.x;
    if (e < E_) {
        int t = tgt[e];
        int key = et[e] * NPB_ + (t >> 7);
        int p = g_bOff[key] + atomicAdd(&g_bFill[key], 1);
        int s = src[e];
        g_eS[p] = s;
        g_eT[p] = t;
        g_eMeta[p] = nt[s] | (nt[t] << 2) | (etm[e] << 4);
    }
}

__global__ void k_init_layer() {
    size_t stride = (size_t)gridDim.x * blockDim.x;
    size_t i0 = (size_t)blockIdx.x * blockDim.x + threadIdx.x;
    for (size_t i = i0; i < 2 * (size_t)N_ * H_; i += stride) g_den[0][i] = 0.f;
    for (size_t i = i0; i < 2 * TD_; i += stride) g_aggr[0][i] = 0.f;
}

// ---------------- GEMM building blocks ----------------
__device__ __forceinline__ void cvt_store(__nv_bfloat16* sAh, __nv_bfloat16* sAl,
                                          int row, int col, float4 v) {
    __nv_bfloat16 h0 = __float2bfloat16_rn(v.x), h1 = __float2bfloat16_rn(v.y);
    __nv_bfloat16 h2 = __float2bfloat16_rn(v.z), h3 = __float2bfloat16_rn(v.w);
    __nv_bfloat16 l0 = __float2bfloat16_rn(v.x - __bfloat162float(h0));
    __nv_bfloat16 l1 = __float2bfloat16_rn(v.y - __bfloat162float(h1));
    __nv_bfloat16 l2 = __float2bfloat16_rn(v.z - __bfloat162float(h2));
    __nv_bfloat16 l3 = __float2bfloat16_rn(v.w - __bfloat162float(h3));
    *(uint2*)(sAh + row * PAD_ + col) = make_uint2(pack_bf2(h0, h1), pack_bf2(h2, h3));
    *(uint2*)(sAl + row * PAD_ + col) = make_uint2(pack_bf2(l0, l1), pack_bf2(l2, l3));
}

// ----- 256-thread loaders (typed_gemm) -----
__device__ __forceinline__ void load_w_smem_half(__nv_bfloat16* sWh, __nv_bfloat16* sWl,
                                                 int midx, int t, int kh, int tid) {
    size_t base = ((size_t)midx * T_ + t) * D_ * D_ + (size_t)kh * 64 * D_;
    const uint4* wh4 = (const uint4*)(g_Wh + base);
    const uint4* wl4 = (const uint4*)(g_Wl + base);
    #pragma unroll
    for (int it = 0; it < 4; it++) {
        int idx = it * 256 + tid;
        int row = idx >> 4;
        int col = (idx & 15) * 8;
        *(uint4*)(sWh + row * PAD_ + col) = wh4[idx];
        *(uint4*)(sWl + row * PAD_ + col) = wl4[idx];
    }
}

// inop: 0=none, 1=gelu(v), 2=gelu(v/den); NT = threads in block
template <int NT>
__device__ __forceinline__ void load_a_smem(__nv_bfloat16* sAh, __nv_bfloat16* sAl,
                                            const float* __restrict__ in,
                                            const int* sList, int inop, int tid,
                                            const float* __restrict__ den) {
    #pragma unroll
    for (int it = 0; it < 4096 / NT; it++) {
        int idx = it * NT + tid;
        int row = idx >> 5;
        int col = (idx & 31) << 2;
        int grow = sList[row];
        float4 v = *(const float4*)(in + (size_t)grow * D_ + col);
        if (inop == 1) {
            v.x = gelu_f(v.x); v.y = gelu_f(v.y); v.z = gelu_f(v.z); v.w = gelu_f(v.w);
        } else if (inop == 2) {
            float dv = den[grow * H_ + (col >> 4)];
            float inv = dv > 0.f ? 1.f / dv : 0.f;
            v.x = gelu_f(v.x * inv); v.y = gelu_f(v.y * inv);
            v.z = gelu_f(v.z * inv); v.w = gelu_f(v.w * inv);
        }
        cvt_store(sAh, sAl, row, col, v);
    }
}

template <int NT>
__device__ __forceinline__ void load_w_smem(__nv_bfloat16* sWh, __nv_bfloat16* sWl,
                                            int midx, int t, int tid) {
    size_t base = ((size_t)midx * T_ + t) * D_ * D_;
    const uint4* wh4 = (const uint4*)(g_Wh + base);
    const uint4* wl4 = (const uint4*)(g_Wl + base);
    #pragma unroll
    for (int it = 0; it < 2048 / NT; it++) {
        int idx = it * NT + tid;
        int row = idx >> 4;
        int col = (idx & 15) * 8;
        *(uint4*)(sWh + row * PAD_ + col) = wh4[idx];
        *(uint4*)(sWl + row * PAD_ + col) = wl4[idx];
    }
}

// K-split mma (256-thread typed_gemm): warp owns 32 rows x 64 cols
__device__ __forceinline__ void mma_tile_ks(float (&acc)[2][8][4],
                                            const __nv_bfloat16* sAh, const __nv_bfloat16* sAl,
                                            const __nv_bfloat16* sWh, const __nv_bfloat16* sWl,
                                            int mbase, int nbase, int lane, int kh) {
    int aRow = mbase + (lane & 15);
    int aColAdd = (lane >> 4) << 3;
    int bg = lane >> 3;
    int bRowAdd = ((bg & 1) << 3) + (lane & 7);
    int bColAdd = (bg >> 1) << 3;

    unsigned aHbase = (unsigned)__cvta_generic_to_shared(sAh + aRow * PAD_);
    unsigned aLbase = (unsigned)__cvta_generic_to_shared(sAl + aRow * PAD_);
    unsigned wHbase = (unsigned)__cvta_generic_to_shared(sWh);
    unsigned wLbase = (unsigned)__cvta_generic_to_shared(sWl);

    #pragma unroll
    for (int kc = 0; kc < 4; kc++) {
        int k0A = kh * 64 + kc * 16;
        int k0W = kc * 16;
        unsigned ah[2][4], al[2][4];
        #pragma unroll
        for (int mt = 0; mt < 2; mt++) {
            unsigned off = (mt * 16 * PAD_ + k0A + aColAdd) * 2;
            ldsm4(ah[mt][0], ah[mt][1], ah[mt][2], ah[mt][3], aHbase + off);
            ldsm4(al[mt][0], al[mt][1], al[mt][2], al[mt][3], aLbase + off);
        }
        #pragma unroll
        for (int nt2 = 0; nt2 < 4; nt2++) {
            int nb = nbase + nt2 * 16;
            unsigned off = ((k0W + bRowAdd) * PAD_ + nb + bColAdd) * 2;
            unsigned bh[4], bl[4];
            ldsm4t(bh[0], bh[1], bh[2], bh[3], wHbase + off);
            ldsm4t(bl[0], bl[1], bl[2], bl[3], wLbase + off);
            #pragma unroll
            for (int mt = 0; mt < 2; mt++) {
                mma16816(acc[mt][nt2 * 2],     ah[mt], bh);
                mma16816(acc[mt][nt2 * 2],     al[mt], bh);
                mma16816(acc[mt][nt2 * 2],     ah[mt], bl);
                mma16816(acc[mt][nt2 * 2 + 1], ah[mt], bh + 2);
                mma16816(acc[mt][nt2 * 2 + 1], al[mt], bh + 2);
                mma16816(acc[mt][nt2 * 2 + 1], ah[mt], bl + 2);
            }
        }
    }
}

// 512-thread mma: warp owns 32 rows x 32 cols (warp grid 4x4)
__device__ __forceinline__ void mma_tile512(float (&acc)[2][4][4],
                                            const __nv_bfloat16* sAh, const __nv_bfloat16* sAl,
                                            const __nv_bfloat16* sWh, const __nv_bfloat16* sWl,
                                            int mbase, int nbase, int lane) {
    int aRow = mbase + (lane & 15);
    int aColAdd = (lane >> 4) << 3;
    int bg = lane >> 3;
    int bRowAdd = ((bg & 1) << 3) + (lane & 7);
    int bColAdd = (bg >> 1) << 3;

    unsigned aHbase = (unsigned)__cvta_generic_to_shared(sAh + aRow * PAD_);
    unsigned aLbase = (unsigned)__cvta_generic_to_shared(sAl + aRow * PAD_);
    unsigned wHbase = (unsigned)__cvta_generic_to_shared(sWh);
    unsigned wLbase = (unsigned)__cvta_generic_to_shared(sWl);

    #pragma unroll
    for (int kc = 0; kc < 8; kc++) {
        int k0 = kc * 16;
        unsigned ah[2][4], al[2][4];
        #pragma unroll
        for (int mt = 0; mt < 2; mt++) {
            unsigned off = (mt * 16 * PAD_ + k0 + aColAdd) * 2;
            ldsm4(ah[mt][0], ah[mt][1], ah[mt][2], ah[mt][3], aHbase + off);
            ldsm4(al[mt][0], al[mt][1], al[mt][2], al[mt][3], aLbase + off);
        }
        #pragma unroll
        for (int nt2 = 0; nt2 < 2; nt2++) {
            int nb = nbase + nt2 * 16;
            unsigned off = ((k0 + bRowAdd) * PAD_ + nb + bColAdd) * 2;
            unsigned bh[4], bl[4];
            ldsm4t(bh[0], bh[1], bh[2], bh[3], wHbase + off);
            ldsm4t(bl[0], bl[1], bl[2], bl[3], wLbase + off);
            #pragma unroll
            for (int mt = 0; mt < 2; mt++) {
                mma16816(acc[mt][nt2 * 2],     ah[mt], bh);
                mma16816(acc[mt][nt2 * 2],     al[mt], bh);
                mma16816(acc[mt][nt2 * 2],     ah[mt], bl);
                mma16816(acc[mt][nt2 * 2 + 1], ah[mt], bh + 2);
                mma16816(acc[mt][nt2 * 2 + 1], al[mt], bh + 2);
                mma16816(acc[mt][nt2 * 2 + 1], ah[mt], bl + 2);
            }
        }
    }
}

// 512-thread block-diag relation transform: warp covers 2 heads (nbase 32-wide)
__device__ __forceinline__ void bd_transform_store512(
    const __nv_bfloat16* sTh, const __nv_bfloat16* sTl,
    const __nv_bfloat16* sBDh, const __nv_bfloat16* sBDl,
    __half* __restrict__ KVout, int koff, const int* sList, int rem,
    int mbase, int nbase, int lane)
{
    int aColAdd = (lane >> 4) << 3;
    int bg = lane >> 3;
    int bRowAdd = ((bg & 1) << 3) + (lane & 7);
    int bColAdd = (bg >> 1) << 3;
    unsigned aHbase = (unsigned)__cvta_generic_to_shared(sTh + (mbase + (lane & 15)) * PAD_);
    unsigned aLbase = (unsigned)__cvta_generic_to_shared(sTl + (mbase + (lane & 15)) * PAD_);
    int rq = lane >> 2, cq = (lane & 3) * 2;

    #pragma unroll
    for (int r = 0; r < R_; r++) {
        unsigned bHbase = (unsigned)__cvta_generic_to_shared(sBDh + r * BDSZ_);
        unsigned bLbase = (unsigned)__cvta_generic_to_shared(sBDl + r * BDSZ_);
        __half* outR = KVout + (size_t)r * N_ * 256 + koff;
        #pragma unroll
        for (int nt2 = 0; nt2 < 2; nt2++) {
            int head = (nbase >> 4) + nt2;
            unsigned ah[2][4], al[2][4];
            #pragma unroll
            for (int mt = 0; mt < 2; mt++) {
                unsigned offA = (mt * 16 * PAD_ + head * 16 + aColAdd) * 2;
                ldsm4(ah[mt][0], ah[mt][1], ah[mt][2], ah[mt][3], aHbase + offA);
                ldsm4(al[mt][0], al[mt][1], al[mt][2], al[mt][3], aLbase + offA);
            }
            unsigned offB = ((head * 16 + bRowAdd) * BDPAD_ + bColAdd) * 2;
            unsigned bh[4], bl[4];
            ldsm4t(bh[0], bh[1], bh[2], bh[3], bHbase + offB);
            ldsm4t(bl[0], bl[1], bl[2], bl[3], bLbase + offB);

            float acc[2][2][4];
            #pragma unroll
            for (int mt = 0; mt < 2; mt++)
                #pragma unroll
                for (int n8 = 0; n8 < 2; n8++)
                    #pragma unroll
                    for (int q = 0; q < 4; q++) acc[mt][n8][q] = 0.f;
            #pragma unroll
            for (int mt = 0; mt < 2; mt++) {
                mma16816(acc[mt][0], ah[mt], bh);
                mma16816(acc[mt][0], al[mt], bh);
                mma16816(acc[mt][0], ah[mt], bl);
                mma16816(acc[mt][1], ah[mt], bh + 2);
                mma16816(acc[mt][1], al[mt], bh + 2);
                mma16816(acc[mt][1], ah[mt], bl + 2);
            }
            #pragma unroll
            for (int mt = 0; mt < 2; mt++) {
                int rl0 = mbase + mt * 16 + rq;
                #pragma unroll
                for (int n8 = 0; n8 < 2; n8++) {
                    int col = head * 16 + n8 * 8 + cq;
                    float* a = acc[mt][n8];
                    #pragma unroll
                    for (int half = 0; half < 2; half++) {
                        int rl = rl0 + half * 8;
                        if (rl < rem)
                            *(__half2*)(outR + (size_t)sList[rl] * 256 + col) =
                                __floats2half2_rn(a[half * 2], a[half * 2 + 1]);
                    }
                }
            }
        }
    }
}

// 512-thread QKV stages over A tile resident in sAh/sAl
__device__ __forceinline__ void qkv_stages512(
    __nv_bfloat16* sAh, __nv_bfloat16* sAl, __nv_bfloat16* sWh, __nv_bfloat16* sWl,
    __nv_bfloat16* sBDh, __nv_bfloat16* sBDl,
    int midx0, int t, const float* Bq, const float* Bk, const float* Bv,
    const __nv_bfloat16* BDhA, const __nv_bfloat16* BDlA,
    const __nv_bfloat16* BDhM, const __nv_bfloat16* BDlM,
    __half* OqH, __half* KVrh,
    const int* sList, int rem, int tid)
{
    int warp = tid >> 5, lane = tid & 31;
    int mbase = (warp & 3) * 32;
    int nbase = (warp >> 2) * 32;
    int rq = lane >> 2, cq = (lane & 3) * 2;

    #pragma unroll
    for (int s = 0; s < 3; s++) {
        if (s > 0) __syncthreads();
        load_w_smem<512>(sWh, sWl, midx0 + s, t, tid);
        __syncthreads();

        float acc[2][4][4];
        #pragma unroll
        for (int i = 0; i < 2; i++)
            #pragma unroll
            for (int j = 0; j < 4; j++)
                #pragma unroll
                for (int q = 0; q < 4; q++) acc[i][j][q] = 0.f;

        mma_tile512(acc, sAh, sAl, sWh, sWl, mbase, nbase, lane);

        const float* Bt = (s == 0 ? Bq : s == 1 ? Bk : Bv) + t * D_;

        if (s == 0) {
            #pragma unroll
            for (int mt = 0; mt < 2; mt++) {
                int rl0 = mbase + mt * 16 + rq;
                #pragma unroll
                for (int nt = 0; nt < 4; nt++) {
                    int col = nbase + nt * 8 + cq;
                    float b0 = Bt[col], b1 = Bt[col + 1];
                    float* a = acc[mt][nt];
                    #pragma unroll
                    for (int half = 0; half < 2; half++) {
                        int rl = rl0 + half * 8;
                        if (rl < rem)
                            *(__half2*)(OqH + (size_t)sList[rl] * D_ + col) =
                                __floats2half2_rn(a[half * 2] + b0, a[half * 2 + 1] + b1);
                    }
                }
            }
        } else {
            __syncthreads();   // all warps done reading sW
            #pragma unroll
            for (int mt = 0; mt < 2; mt++) {
                int rl0 = mbase + mt * 16 + rq;
                #pragma unroll
                for (int nt = 0; nt < 4; nt++) {
                    int col = nbase + nt * 8 + cq;
                    float b0 = Bt[col], b1 = Bt[col + 1];
                    float* a = acc[mt][nt];
                    #pragma unroll
                    for (int half = 0; half < 2; half++) {
                        int row = rl0 + half * 8;
                        float v0 = a[half * 2] + b0, v1 = a[half * 2 + 1] + b1;
                        __nv_bfloat16 h0 = __float2bfloat16_rn(v0);
                        __nv_bfloat16 h1 = __float2bfloat16_rn(v1);
                        __nv_bfloat16 l0 = __float2bfloat16_rn(v0 - __bfloat162float(h0));
                        __nv_bfloat16 l1 = __float2bfloat16_rn(v1 - __bfloat162float(h1));
                        *(unsigned*)(sWh + row * PAD_ + col) = pack_bf2(h0, h1);
                        *(unsigned*)(sWl + row * PAD_ + col) = pack_bf2(l0, l1);
                    }
                }
            }
            {
                const uint4* gh = (const uint4*)(s == 1 ? BDhA : BDhM);
                const uint4* gl = (const uint4*)(s == 1 ? BDlA : BDlM);
                uint4* dh = (uint4*)sBDh;
                uint4* dl = (uint4*)sBDl;
                #pragma unroll
                for (int it = 0; it < (R_ * BDSZ_ / 8 + 511) / 512; it++) {
                    int i = it * 512 + tid;
                    if (i < R_ * BDSZ_ / 8) { dh[i] = gh[i]; dl[i] = gl[i]; }
                }
            }
            __syncthreads();
            bd_transform_store512(sWh, sWl, sBDh, sBDl, KVrh, (s == 1 ? 0 : 128),
                                  sList, rem, mbase, nbase, lane);
        }
    }
}

// ---------------- QKV + relation-transform GEMM (512 threads) ----------------
__global__ void __launch_bounds__(512) k_qkvr_gemm(
    const float* __restrict__ in, int midx0,
    const float* __restrict__ Bq, const float* __restrict__ Bk, const float* __restrict__ Bv,
    const __nv_bfloat16* __restrict__ BDhA, const __nv_bfloat16* __restrict__ BDlA,
    const __nv_bfloat16* __restrict__ BDhM, const __nv_bfloat16* __restrict__ BDlM,
    __half* __restrict__ OqH, __half* __restrict__ KVrh)
{
    int t = blockIdx.y;
    int cnt = g_typeCnt[t];
    int base = blockIdx.x * 128;
    if (base >= cnt) return;
    const int* list = &g_typeList[t][base];
    int rem = cnt - base; if (rem > 128) rem = 128;

    extern __shared__ __nv_bfloat16 sm[];
    __nv_bfloat16* sAh = sm;
    __nv_bfloat16* sAl = sAh + 128 * PAD_;
    __nv_bfloat16* sWh = sAl + 128 * PAD_;
    __nv_bfloat16* sWl = sWh + 128 * PAD_;
    __nv_bfloat16* sBDh = sWl + 128 * PAD_;
    __nv_bfloat16* sBDl = sBDh + R_ * BDSZ_;
    __shared__ int sList[128];

    int tid = threadIdx.x;
    if (tid < 128) sList[tid] = (tid < rem) ? list[tid] : list[0];
    __syncthreads();

    load_a_smem<512>(sAh, sAl, in, sList, 0, tid, nullptr);

    qkv_stages512(sAh, sAl, sWh, sWl, sBDh, sBDl, midx0, t, Bq, Bk, Bv,
                  BDhA, BDlA, BDhM, BDlM, OqH, KVrh, sList, rem, tid);
}

// ---------------- fused trans + next-layer QKV (512 threads) ----------------
__global__ void __launch_bounds__(512) k_trans_qkvr(
    const float* __restrict__ inA, int midxA,
    const float* __restrict__ BbaseA, float* __restrict__ outA,
    const float* __restrict__ prev, const float* __restrict__ skipv,
    const float* __restrict__ den,
    int midxQ,
    const float* __restrict__ Bq, const float* __restrict__ Bk, const float* __restrict__ Bv,
    const __nv_bfloat16* __restrict__ BDhA, const __nv_bfloat16* __restrict__ BDlA,
    const __nv_bfloat16* __restrict__ BDhM, const __nv_bfloat16* __restrict__ BDlM,
    __half* __restrict__ OqH, __half* __restrict__ KVrh)
{
    int t = blockIdx.y;
    int cnt = g_typeCnt[t];
    int base = blockIdx.x * 128;
    if (base >= cnt) return;
    const int* list = &g_typeList[t][base];
    int rem = cnt - base; if (rem > 128) rem = 128;

    extern __shared__ __nv_bfloat16 sm[];
    __nv_bfloat16* sAh = sm;
    __nv_bfloat16* sAl = sAh + 128 * PAD_;
    __nv_bfloat16* sWh = sAl + 128 * PAD_;
    __nv_bfloat16* sWl = sWh + 128 * PAD_;
    __nv_bfloat16* sBDh = sWl + 128 * PAD_;
    __nv_bfloat16* sBDl = sBDh + R_ * BDSZ_;
    __shared__ int sList[128];

    int tid = threadIdx.x;
    if (tid < 128) sList[tid] = (tid < rem) ? list[tid] : list[0];
    __syncthreads();

    load_a_smem<512>(sAh, sAl, inA, sList, 2, tid, den);
    load_w_smem<512>(sWh, sWl, midxA, t, tid);
    __syncthreads();

    int warp = tid >> 5, lane = tid & 31;
    int mbase = (warp & 3) * 32;
    int nbase = (warp >> 2) * 32;
    int rq = lane >> 2, cq = (lane & 3) * 2;

    float acc[2][4][4];
    #pragma unroll
    for (int i = 0; i < 2; i++)
        #pragma unroll
        for (int j = 0; j < 4; j++)
            #pragma unroll
            for (int q = 0; q < 4; q++) acc[i][j][q] = 0.f;

    mma_tile512(acc, sAh, sAl, sWh, sWl, mbase, nbase, lane);
    __syncthreads();   // all warps done reading sAh/sAl (cross-warp row sharing)

    {
        const float* Bt = BbaseA + t * D_;
        float alpha = 1.f / (1.f + expf(-skipv[t]));
        float beta = 1.f - alpha;
        #pragma unroll
        for (int mt = 0; mt < 2; mt++) {
            int rl0 = mbase + mt * 16 + rq;
            #pragma unroll
            for (int nt = 0; nt < 4; nt++) {
                int col = nbase + nt * 8 + cq;
                float b0 = Bt[col], b1 = Bt[col + 1];
                float* a = acc[mt][nt];
                #pragma unroll
                for (int half = 0; half < 2; half++) {
                    int row = rl0 + half * 8;
                    int grow = sList[row];
                    const float* pp = prev + (size_t)grow * D_ + col;
                    float2 old = *(const float2*)pp;
                    float v0 = alpha * (a[half * 2]     + b0) + beta * old.x;
                    float v1 = alpha * (a[half * 2 + 1] + b1) + beta * old.y;
                    if (row < rem)
                        *(float2*)(outA + (size_t)grow * D_ + col) = make_float2(v0, v1);
                    __nv_bfloat16 h0 = __float2bfloat16_rn(v0);
                    __nv_bfloat16 h1 = __float2bfloat16_rn(v1);
                    __nv_bfloat16 l0 = __float2bfloat16_rn(v0 - __bfloat162float(h0));
                    __nv_bfloat16 l1 = __float2bfloat16_rn(v1 - __bfloat162float(h1));
                    *(unsigned*)(sAh + row * PAD_ + col) = pack_bf2(h0, h1);
                    *(unsigned*)(sAl + row * PAD_ + col) = pack_bf2(l0, l1);
                }
            }
        }
    }
    qkv_stages512(sAh, sAl, sWh, sWl, sBDh, sBDl, midxQ, t, Bq, Bk, Bv,
                  BDhA, BDlA, BDhM, BDlM, OqH, KVrh, sList, rem, tid);
}

// ---------------- single typed GEMM (adapt / final trans), K-split W, 2 CTA/SM ----------------
__global__ void __launch_bounds__(256, 2) k_typed_gemm(
    int inop, int outop,
    const float* __restrict__ in, int midx,
    const float* __restrict__ Bbase,
    float* __restrict__ out,
    const float* __restrict__ prev,
    const float* __restrict__ skipv,
    const float* __restrict__ den)
{
    int t = blockIdx.y;
    int cnt = g_typeCnt[t];
    int base = blockIdx.x * 128;
    if (base >= cnt) return;
    const int* list = &g_typeList[t][base];
    int rem = cnt - base; if (rem > 128) rem = 128;

    extern __shared__ __nv_bfloat16 sm[];
    __nv_bfloat16* sAh = sm;
    __nv_bfloat16* sAl = sAh + 128 * PAD_;
    __nv_bfloat16* sWh = sAl + 128 * PAD_;      // 64-row half buffer
    __nv_bfloat16* sWl = sWh + 64 * PAD_;
    __shared__ int sList[128];

    int tid = threadIdx.x;
    if (tid < 128) sList[tid] = (tid < rem) ? list[tid] : list[0];
    __syncthreads();

    load_a_smem<256>(sAh, sAl, in, sList, inop, tid, den);
    load_w_smem_half(sWh, sWl, midx, t, 0, tid);
    __syncthreads();

    int warp = tid >> 5, lane = tid & 31;
    int mbase = (warp & 3) * 32;
    int nbase = (warp >> 2) * 64;

    float acc[2][8][4];
    #pragma unroll
    for (int i = 0; i < 2; i++)
        #pragma unroll
        for (int j = 0; j < 8; j++)
            #pragma unroll
            for (int q = 0; q < 4; q++) acc[i][j][q] = 0.f;

    mma_tile_ks(acc, sAh, sAl, sWh, sWl, mbase, nbase, lane, 0);
    __syncthreads();
    load_w_smem_half(sWh, sWl, midx, t, 1, tid);
    __syncthreads();
    mma_tile_ks(acc, sAh, sAl, sWh, sWl, mbase, nbase, lane, 1);

    const float* Bt = Bbase + t * D_;
    float alpha = 0.f, beta = 0.f;
    if (outop == 2) { alpha = 1.f / (1.f + expf(-skipv[t])); beta = 1.f - alpha; }

    int rq = lane >> 2, cq = (lane & 3) * 2;
    #pragma unroll
    for (int mt = 0; mt < 2; mt++) {
        int rl0 = mbase + mt * 16 + rq;
        #pragma unroll
        for (int nt = 0; nt < 8; nt++) {
            int col = nbase + nt * 8 + cq;
            float b0 = Bt[col], b1 = Bt[col + 1];
            float* a = acc[mt][nt];
            #pragma unroll
            for (int half = 0; half < 2; half++) {
                int rl = rl0 + half * 8;
                if (rl < rem) {
                    int grow = sList[rl];
                    float v0 = a[half * 2]     + b0;
                    float v1 = a[half * 2 + 1] + b1;
                    if (outop == 1) { v0 = tanhf(v0); v1 = tanhf(v1); }
                    else if (outop == 2) {
                        const float* pp = prev + (size_t)grow * D_ + col;
                        float2 old = *(const float2*)pp;
                        v0 = alpha * v0 + beta * old.x;
                        v1 = alpha * v1 + beta * old.y;
                    }
                    *(float2*)(out + (size_t)grow * D_ + col) = make_float2(v0, v1);
                }
            }
        }
    }
}

// ---------------- fused edge pass (lean body, occupancy-forced) ----------------
__global__ void __launch_bounds__(256, 4) k_edgeAC(const __half* __restrict__ tabKV,
                                                   const float* __restrict__ relPri,
                                                   float* __restrict__ aggr,
                                                   float* __restrict__ den) {
    int r = blockIdx.y;
    int lo = g_bOff[r * NPB_], hi = g_bOff[(r + 1) * NPB_];
    int lane = threadIdx.x & 31;
    int h = lane & 7, esub = lane >> 3;
    int warp = blockIdx.x * (blockDim.x >> 5) + (threadIdx.x >> 5);
    int nwarp = gridDim.x * (blockDim.x >> 5);
    const __half* KVr = g_KVrh + (size_t)r * N_ * 256;
    const __half* tabR = tabKV + (size_t)r * T_ * ML_ * 256;

    for (int eb = lo + warp * 4; eb < hi; eb += nwarp * 4) {
        int p = eb + esub;
        bool valid = p < hi;
        int pp = valid ? p : lo;
        int s = g_eS[pp], t = g_eT[pp], meta = g_eMeta[pp];
        int st = meta & 3, tt = (meta >> 2) & 3, tm = meta >> 4;
        const __half* kvb = KVr + (size_t)s * 256 + h * 16;
        const __half* tbb = tabR + (size_t)(st * ML_ + tm) * 256 + h * 16;

        const uint4* kp = (const uint4*)kvb;
        const uint4* qp = (const uint4*)(g_Qh + (size_t)t * D_ + h * 16);
        const uint4* tp = (const uint4*)tbb;
        __half2 kh[8], qh[8], th[8];
        *(uint4*)(kh) = kp[0]; *(uint4*)(kh + 4) = kp[1];
        *(uint4*)(qh) = qp[0]; *(uint4*)(qh + 4) = qp[1];
        *(uint4*)(th) = tp[0]; *(uint4*)(th + 4) = tp[1];
        float sc = 0.f;
        #pragma unroll
        for (int i = 0; i < 8; i++) {
            float2 kf = __half22float2(kh[i]);
            float2 qf = __half22float2(qh[i]);
            float2 tf = __half22float2(th[i]);
            sc += qf.x * (kf.x + tf.x) + qf.y * (kf.y + tf.y);
        }
        float pri = relPri[((tt * R_ + r) * T_ + st) * H_ + h];
        // scores are O(1): exp without max-subtraction cannot overflow fp32;
        // softmax is shift-invariant so result is exact.
        float ex = expf(sc * pri * 0.25f);

        const uint4* vp = (const uint4*)(kvb + 128);
        const uint4* tvp = (const uint4*)(tbb + 128);
        __half2 vh[8], tvh[8];
        *(uint4*)(vh) = vp[0]; *(uint4*)(vh + 4) = vp[1];
        *(uint4*)(tvh) = tvp[0]; *(uint4*)(tvh + 4) = tvp[1];

        if (valid) {
            atomicAdd(&den[t * H_ + h], ex);
            float* op = aggr + (size_t)t * D_ + h * 16;
            #pragma unroll
            for (int i = 0; i < 4; i++) {
                float2 a = __half22float2(vh[2 * i]);
                float2 b = __half22float2(vh[2 * i + 1]);
                float2 ta = __half22float2(tvh[2 * i]);
                float2 tb = __half22float2(tvh[2 * i + 1]);
                red_add_v4(op + i * 4,
                           (a.x + ta.x) * ex, (a.y + ta.y) * ex,
                           (b.x + tb.x) * ex, (b.y + tb.y) * ex);
            }
        }
    }
}

// ---------------- launch ----------------
static cudaStream_t s1 = nullptr, s2 = nullptr, s3 = nullptr;
static cudaEvent_t evF = nullptr, evBuck = nullptr, evInit = nullptr;
static cudaEvent_t evTab0 = nullptr, evTab1 = nullptr, evW0 = nullptr, evW1 = nullptr;

extern "C" void kernel_launch(void* const* d_in, const int* in_sizes, int n_in,
                              void* d_out, int out_size) {
    const float* node_feature = (const float*)d_in[0];
    const int*   node_type    = (const int*)d_in[1];
    const int*   edge_index   = (const int*)d_in[2];
    const int*   edge_type    = (const int*)d_in[3];
    const int*   edge_time    = (const int*)d_in[4];
    const float* adapt_w      = (const float*)d_in[5];
    const float* adapt_b      = (const float*)d_in[6];
    const float* Wk           = (const float*)d_in[7];
    const float* bk           = (const float*)d_in[8];
    const float* Wq           = (const float*)d_in[9];
    const float* bq           = (const float*)d_in[10];
    const float* Wv           = (const float*)d_in[11];
    const float* bv           = (const float*)d_in[12];
    const float* Wa           = (const float*)d_in[13];
    const float* ba           = (const float*)d_in[14];
    const float* rel_pri      = (const float*)d_in[15];
    const float* rel_att      = (const float*)d_in[16];
    const float* rel_msg      = (const float*)d_in[17];
    const float* skip         = (const float*)d_in[18];
    const float* rte_w        = (const float*)d_in[19];
    const float* rte_b        = (const float*)d_in[20];

    const int* src = edge_index;
    const int* tgt = edge_index + E_;

    if (!s1) {
        cudaStreamCreateWithFlags(&s1, cudaStreamNonBlocking);
        cudaStreamCreateWithFlags(&s2, cudaStreamNonBlocking);
        cudaStreamCreateWithFlags(&s3, cudaStreamNonBlocking);
        cudaEventCreateWithFlags(&evF, cudaEventDisableTiming);
        cudaEventCreateWithFlags(&evBuck, cudaEventDisableTiming);
        cudaEventCreateWithFlags(&evInit, cudaEventDisableTiming);
        cudaEventCreateWithFlags(&evTab0, cudaEventDisableTiming);
        cudaEventCreateWithFlags(&evTab1, cudaEventDisableTiming);
        cudaEventCreateWithFlags(&evW0, cudaEventDisableTiming);
        cudaEventCreateWithFlags(&evW1, cudaEventDisableTiming);
        cudaFuncSetAttribute(k_typed_gemm, cudaFuncAttributeMaxDynamicSharedMemorySize, GEMM_SMEM);
        cudaFuncSetAttribute(k_qkvr_gemm, cudaFuncAttributeMaxDynamicSharedMemorySize, QKVR_SMEM);
        cudaFuncSetAttribute(k_trans_qkvr, cudaFuncAttributeMaxDynamicSharedMemorySize, QKVR_SMEM);
    }

    float *px, *pa0, *pa1, *pd0, *pd1;
    __half *pQh, *pKVrh, *ptKV0;
    __nv_bfloat16 *pBDh, *pBDl;
    cudaGetSymbolAddress((void**)&px, g_x);
    cudaGetSymbolAddress((void**)&pQh, g_Qh);
    cudaGetSymbolAddress((void**)&pa0, g_aggr);
    pa1 = pa0 + TD_;
    cudaGetSymbolAddress((void**)&pd0, g_den);
    pd1 = pd0 + N_ * H_;
    cudaGetSymbolAddress((void**)&pKVrh, g_KVrh);
    cudaGetSymbolAddress((void**)&ptKV0, g_tabKVh);
    cudaGetSymbolAddress((void**)&pBDh, g_BDh);
    cudaGetSymbolAddress((void**)&pBDl, g_BDl);
    const size_t TABSTRIDE = (size_t)R_ * T_ * ML_ * 256;

    dim3 ggrid((N_ + 127) / 128, T_);
    dim3 egrid(256, R_);
    const int WSPLIT_GRID = (T_ * D_ * D_ + 255) / 256;
    size_t woff1 = (size_t)T_ * 128 * 128;

    // fork all three side streams from the capture origin
    cudaEventRecord(evF, 0);
    cudaStreamWaitEvent(s1, evF, 0);
    cudaStreamWaitEvent(s2, evF, 0);
    cudaStreamWaitEvent(s3, evF, 0);

    // s1: edge bucketing + layer-buffer zeroing
    k_init_bkt<<<(NB_ + 255) / 256, 256, 0, s1>>>();
    k_count_b<<<(E_ + 255) / 256, 256, 0, s1>>>(tgt, edge_type);
    k_scan_b<<<1, 1024, 0, s1>>>();
    k_scatter_b<<<(E_ + 255) / 256, 256, 0, s1>>>(src, tgt, edge_type, edge_time, node_type);
    cudaEventRecord(evBuck, s1);
    k_init_layer<<<2048, 256, 0, s1>>>();
    cudaEventRecord(evInit, s1);

    // s2: RTE tables (layer 0 then layer 1)
    k_rte_tab<<<ML_, 128, 0, s2>>>();
    k_rte_proj<<<ML_, 128, 0, s2>>>(rte_w, rte_b);
    k_tables<<<T_ * ML_, 128, 0, s2>>>(Wk, Wv, rel_att, rel_msg, 0);
    cudaEventRecord(evTab0, s2);
    k_rte_proj<<<ML_, 128, 0, s2>>>(rte_w + (size_t)256 * 128, rte_b + 128);
    k_tables<<<T_ * ML_, 128, 0, s2>>>(Wk + woff1, Wv + woff1,
                                       rel_att + (size_t)R_ * H_ * 256,
                                       rel_msg + (size_t)R_ * H_ * 256, 1);
    cudaEventRecord(evTab1, s2);

    // s3: weight splits (layer-0 QKV first, then the rest)
    k_relsplit<<<(2 * 2 * R_ * H_ * 256 + 255) / 256, 256, 0, s3>>>(rel_att, rel_msg);
    k_wsplit<<<WSPLIT_GRID, 256, 0, s3>>>(Wq, 1);
    k_wsplit<<<WSPLIT_GRID, 256, 0, s3>>>(Wk, 2);
    k_wsplit<<<WSPLIT_GRID, 256, 0, s3>>>(Wv, 3);
    cudaEventRecord(evW0, s3);
    k_wsplit<<<WSPLIT_GRID, 256, 0, s3>>>(Wa, 4);
    k_wsplit<<<WSPLIT_GRID, 256, 0, s3>>>(Wq + woff1, 5);
    k_wsplit<<<WSPLIT_GRID, 256, 0, s3>>>(Wk + woff1, 6);
    k_wsplit<<<WSPLIT_GRID, 256, 0, s3>>>(Wv + woff1, 7);
    k_wsplit<<<WSPLIT_GRID, 256, 0, s3>>>(Wa + woff1, 8);
    cudaEventRecord(evW1, s3);

    // main: type buckets + adapt GEMM
    k_init_type<<<1, 32>>>();
    k_build_type<<<(N_ + 255) / 256, 256>>>(node_type);
    k_wsplit<<<WSPLIT_GRID, 256>>>(adapt_w, 0);
    k_typed_gemm<<<ggrid, 256, GEMM_SMEM>>>(0, 1, node_feature, 0, adapt_b, px, px, nullptr, nullptr);

    cudaStreamWaitEvent(0, evW0, 0);   // Wq/Wk/Wv(l0) + BD splits ready
    k_qkvr_gemm<<<ggrid, 512, QKVR_SMEM>>>(
        px, 1, bq, bk, bv,
        pBDh + 0 * R_ * BDSZ_, pBDl + 0 * R_ * BDSZ_,
        pBDh + 1 * R_ * BDSZ_, pBDl + 1 * R_ * BDSZ_,
        pQh, pKVrh);

    cudaStreamWaitEvent(0, evBuck, 0);
    cudaStreamWaitEvent(0, evTab0, 0);
    cudaStreamWaitEvent(0, evInit, 0);
    k_edgeAC<<<egrid, 256>>>(ptKV0, rel_pri, pa0, pd0);

    cudaStreamWaitEvent(0, evW1, 0);   // Wa(l0) + l1 weights ready
    k_trans_qkvr<<<ggrid, 512, QKVR_SMEM>>>(
        pa0, 4, ba, px, px, skip, pd0,
        5, bq + T_ * 128, bk + T_ * 128, bv + T_ * 128,
        pBDh + 2 * R_ * BDSZ_, pBDl + 2 * R_ * BDSZ_,
        pBDh + 3 * R_ * BDSZ_, pBDl + 3 * R_ * BDSZ_,
        pQh, pKVrh);

    cudaStreamWaitEvent(0, evTab1, 0);
    k_edgeAC<<<egrid, 256>>>(ptKV0 + TABSTRIDE, rel_pri + (size_t)T_ * R_ * T_ * H_, pa1, pd1);

    // final trans -> d_out
    k_typed_gemm<<<ggrid, 256, GEMM_SMEM>>>(2, 2, pa1, 8, ba + T_ * 128,
                                            (float*)d_out, px, skip + T_, pd1);
}